// round 12
// baseline (speedup 1.0000x reference)
#include <cuda_runtime.h>
#include <cuda_bf16.h>
#include <math.h>
#include <stdint.h>

typedef unsigned long long u64;

#define NMAX 50000
#define EMAX 640000

__device__ float g_x[(size_t)NMAX * 128];
__device__ float g_sums[(size_t)NMAX * 128];
__device__ float g_cnt[NMAX];
__device__ __align__(16) char g_w1s[128 * 128];   // W_fg1^T, K=64, 128B/row, swizzled
__device__ __align__(16) char g_w2s[128 * 256];   // W_fg2^T, K=128, 256B/row, swizzled
__device__ __align__(16) __nv_bfloat16 g_wa1b[128 * 136];
__device__ __align__(16) __nv_bfloat16 g_wa2b[128 * 136];
__device__ __align__(16) __nv_bfloat16 g_wa3b[128 * 136];

__device__ __forceinline__ float sp_fast(float x) {
    float t = __expf(-fabsf(x));
    return fmaxf(x, 0.f) + __logf(1.f + t) - 0.69314718055994531f;
}
__device__ __forceinline__ uint32_t smem_u32(const void* p) {
    uint32_t a;
    asm("{ .reg .u64 t; cvta.to.shared.u64 t, %1; cvt.u32.u64 %0, t; }" : "=r"(a) : "l"(p));
    return a;
}
__device__ __forceinline__ void ldsm4(uint32_t& r0, uint32_t& r1, uint32_t& r2, uint32_t& r3, uint32_t addr) {
    asm volatile("ldmatrix.sync.aligned.m8n8.x4.shared.b16 {%0,%1,%2,%3}, [%4];"
                 : "=r"(r0), "=r"(r1), "=r"(r2), "=r"(r3) : "r"(addr));
}
__device__ __forceinline__ void mma16(float d[4], const uint32_t a[4], uint32_t b0, uint32_t b1) {
    asm("mma.sync.aligned.m16n8k16.row.col.f32.bf16.bf16.f32 "
        "{%0,%1,%2,%3}, {%4,%5,%6,%7}, {%8,%9}, {%0,%1,%2,%3};"
        : "+f"(d[0]), "+f"(d[1]), "+f"(d[2]), "+f"(d[3])
        : "r"(a[0]), "r"(a[1]), "r"(a[2]), "r"(a[3]), "r"(b0), "r"(b1));
}
__device__ __forceinline__ uint32_t pack_bf(float lo, float hi) {
    __nv_bfloat162 p = __floats2bfloat162_rn(lo, hi);
    return *(uint32_t*)&p;
}
__device__ __forceinline__ uint32_t swz2(int row, int chunk, int RB) {
    return (uint32_t)(row * RB + (((chunk ^ (row & 7)) & (RB / 16 - 1)) << 4));
}
__device__ __forceinline__ void barx(int id) {
    asm volatile("bar.sync %0, 256;" :: "r"(id) : "memory");
}

__device__ __forceinline__ void zero8(float acc[2][8][4]) {
    #pragma unroll
    for (int a = 0; a < 2; a++)
        #pragma unroll
        for (int b = 0; b < 8; b++)
            #pragma unroll
            for (int c = 0; c < 4; c++) acc[a][b][c] = 0.f;
}

// ---- swizzled warp GEMM, 32(m) x 64(n) warp tile ----
template<int K, int RBA, int RBB>
__device__ __forceinline__ void wgemm_sw64(uint32_t Au, int arow, int ak,
                                           uint32_t Bu, int brow0, int bk,
                                           float acc[2][8][4]) {
    #pragma unroll
    for (int kk = 0; kk < K; kk += 16) {
        int kc = kk >> 3;
        uint32_t a[2][4];
        #pragma unroll
        for (int mt = 0; mt < 2; mt++)
            ldsm4(a[mt][0], a[mt][1], a[mt][2], a[mt][3], Au + swz2(arow + mt * 16, kc + ak, RBA));
        #pragma unroll
        for (int p = 0; p < 4; p++) {
            uint32_t b0, b1, b2, b3;
            ldsm4(b0, b1, b2, b3, Bu + swz2(brow0 + p * 16, kc + bk, RBB));
            mma16(acc[0][2 * p], a[0], b0, b1);
            mma16(acc[1][2 * p], a[1], b0, b1);
            mma16(acc[0][2 * p + 1], a[0], b2, b3);
            mma16(acc[1][2 * p + 1], a[1], b2, b3);
        }
    }
}

// ---- padded non-swizzled warp GEMM (node / x kernels), 32x64 tile ----
template<int K, int S>
__device__ __forceinline__ void wgemm(uint32_t Abase, uint32_t Bbase, float acc[2][8][4]) {
    #pragma unroll
    for (int kk = 0; kk < K; kk += 16) {
        uint32_t a[2][4];
        #pragma unroll
        for (int mt = 0; mt < 2; mt++)
            ldsm4(a[mt][0], a[mt][1], a[mt][2], a[mt][3], Abase + (mt * 16 * S + kk) * 2);
        #pragma unroll
        for (int p = 0; p < 4; p++) {
            uint32_t b0, b1, b2, b3;
            ldsm4(b0, b1, b2, b3, Bbase + (p * 16 * S + kk) * 2);
            mma16(acc[0][2 * p], a[0], b0, b1);
            mma16(acc[1][2 * p], a[1], b0, b1);
            mma16(acc[0][2 * p + 1], a[0], b2, b3);
            mma16(acc[1][2 * p + 1], a[1], b2, b3);
        }
    }
}

__global__ void prep_weights(const float* __restrict__ W1, const float* __restrict__ W2,
                             const float* __restrict__ Wa1, const float* __restrict__ Wa2,
                             const float* __restrict__ Wa3) {
    int t = blockIdx.x * blockDim.x + threadIdx.x;
    int stride = blockDim.x * gridDim.x;
    for (int i = t; i < 64 * 128; i += stride) {
        int k = i >> 7, n = i & 127;
        *(__nv_bfloat16*)(g_w1s + swz2(n, k >> 3, 128) + (k & 7) * 2) = __float2bfloat16(W1[i]);
    }
    for (int i = t; i < 128 * 128; i += stride) {
        int k = i >> 7, n = i & 127;
        *(__nv_bfloat16*)(g_w2s + swz2(n, k >> 3, 256) + (k & 7) * 2) = __float2bfloat16(W2[i]);
        g_wa1b[n * 136 + k] = __float2bfloat16(Wa1[i]);
        g_wa2b[n * 136 + k] = __float2bfloat16(Wa2[i]);
        g_wa3b[n * 136 + k] = __float2bfloat16(Wa3[i]);
    }
}

__global__ void dummy_kernel() {}

#define XK_SMEM ((128 * 136 * 2) * 2)
__global__ __launch_bounds__(256, 2) void gemm_x_mma(const float* __restrict__ A,
                                                     int N, int ntiles) {
    extern __shared__ char smc[];
    __nv_bfloat16* Wt = (__nv_bfloat16*)smc;
    __nv_bfloat16* As = Wt + 128 * 136;
    int tid = threadIdx.x, wid = tid >> 5, lane = tid & 31;
    int g = lane >> 2, q = lane & 3;
    int mw = wid & 3, nw = wid >> 2;
    int arow = (lane & 7) + ((lane >> 3) & 1) * 8, ak = lane >> 4;
    int brow = (lane & 7) + ((lane >> 4) << 3), bk = (lane >> 3) & 1;

    for (int i = tid; i < 128 * 136 * 2 / 16; i += 256) ((uint4*)Wt)[i] = ((const uint4*)g_wa1b)[i];
    uint32_t Ab = smem_u32(As) + ((mw * 32 + arow) * 136 + ak * 8) * 2;
    uint32_t Bb = smem_u32(Wt) + ((nw * 64 + brow) * 136 + bk * 8) * 2;

    for (int t = blockIdx.x; t < ntiles; t += gridDim.x) {
        int r0 = t * 128;
        #pragma unroll
        for (int c = 0; c < 16; c++) {
            int ci = c * 256 + tid;
            int m = ci >> 5, qq = ci & 31;
            int r = r0 + m;
            float4 v = {0.f, 0.f, 0.f, 0.f};
            if (r < N) v = ((const float4*)A)[(size_t)r * 32 + qq];
            uint2 pv = {pack_bf(v.x, v.y), pack_bf(v.z, v.w)};
            *(uint2*)((char*)As + (m * 136 + qq * 4) * 2) = pv;
        }
        __syncthreads();
        float acc[2][8][4];
        zero8(acc);
        wgemm<128, 136>(Ab, Bb, acc);
        #pragma unroll
        for (int mt = 0; mt < 2; mt++) {
            int rlo = r0 + mw * 32 + mt * 16 + g, rhi = rlo + 8;
            #pragma unroll
            for (int nt = 0; nt < 8; nt++) {
                int c0 = nw * 64 + nt * 8 + 2 * q;
                if (rlo < N) *(float2*)(g_x + (size_t)rlo * 128 + c0) = make_float2(acc[mt][nt][0], acc[mt][nt][1]);
                if (rhi < N) *(float2*)(g_x + (size_t)rhi * 128 + c0) = make_float2(acc[mt][nt][2], acc[mt][nt][3]);
            }
        }
        __syncthreads();
    }
}

// ---------------- Kernel 2: 512-thread edge kernel, two named-barrier half-CTAs ----------------
// shared: W1 16K @0, W2 32K @16384, b1s @49152, b2s @49664
// per half (base 50176 + half*83968): A1 16K @0, A2 32K @16384, P(bf16 w) 32K @49152,
//                                     i1[2][128] @81920, i2[2][128] @82944
#define HW1 0
#define HW2 16384
#define HB1 49152
#define HB2 49664
#define HBASE 50176
#define HSZ 83968
#define HA1 0
#define HA2 16384
#define HP  49152
#define HI1 81920
#define HI2 82944
#define EDGE_SMEM (HBASE + 2 * HSZ)   // 218112

__global__ __launch_bounds__(512, 1) void edge_mma_kernel(const float* __restrict__ ef,
                                                          const int* __restrict__ idx1,
                                                          const int* __restrict__ idx2,
                                                          const float* __restrict__ b1,
                                                          const float* __restrict__ b2,
                                                          int E, int ntiles) {
    extern __shared__ char smc[];
    float* b1s = (float*)(smc + HB1);
    float* b2s = (float*)(smc + HB2);

    int tid = threadIdx.x;
    int half = tid >> 8;
    int h = tid & 255;
    int wid = h >> 5, lane = h & 31;
    int g = lane >> 2, q = lane & 3;
    int mw = wid & 3, nw = wid >> 2;          // 4(m) x 2(n), 32x64 warp tiles
    int arow_l = (lane & 7) + ((lane >> 3) & 1) * 8, ak = lane >> 4;
    int brow_l = (lane & 7) + ((lane >> 4) << 3), bk = (lane >> 3) & 1;
    const float4* ef4 = (const float4*)ef;

    char* hb = smc + HBASE + half * HSZ;
    int* i1b = (int*)(hb + HI1);
    int* i2b = (int*)(hb + HI2);

    // weights + biases loaded by all 512 threads
    for (int i = tid; i < 16384 / 16; i += 512) ((uint4*)(smc + HW1))[i] = ((const uint4*)g_w1s)[i];
    for (int i = tid; i < 32768 / 16; i += 512) ((uint4*)(smc + HW2))[i] = ((const uint4*)g_w2s)[i];
    if (tid < 128) { b1s[tid] = b1[tid]; b2s[tid] = b2[tid]; }

    uint32_t W1u = smem_u32(smc + HW1), W2u = smem_u32(smc + HW2);
    uint32_t A1u = smem_u32(hb + HA1), A2u = smem_u32(hb + HA2);

    int arow = mw * 32 + arow_l;
    int brow0 = nw * 64 + brow_l;
    int barid = 1 + half;
    int par = 0;

    __syncthreads();   // weights visible to both halves

    int t = blockIdx.x * 2 + half;
    int tstep = gridDim.x * 2;

    if (t < ntiles) {
        int e0 = t * 128;
        #pragma unroll
        for (int c = 0; c < 8; c++) {
            int ci = c * 256 + h;
            int m = ci >> 4, qq = ci & 15;
            int e = e0 + m;
            float4 v = {0.f, 0.f, 0.f, 0.f};
            if (e < E) v = ef4[(size_t)e * 16 + qq];
            uint2 pv = {pack_bf(v.x, v.y), pack_bf(v.z, v.w)};
            *(uint2*)(hb + HA1 + swz2(m, qq >> 1, 128) + (qq & 1) * 8) = pv;
        }
        {
            int e = e0 + (h & 127);
            int v = (e < E) ? ((h < 128) ? idx1[e] : idx2[e]) : 0;
            if (h < 128) i1b[h] = v; else i2b[h - 128] = v;
        }
    }
    barx(barid);   // prologue: A1(t0)+idx[0] visible within half

    for (; t < ntiles; t += tstep) {
        int e0 = t * 128;
        int tn = t + tstep;
        bool have_next = tn < ntiles;

        // register-prefetch next tile's edge features + indices
        float4 pf[8];
        int pidx = 0;
        if (have_next) {
            int ee0 = tn * 128;
            #pragma unroll
            for (int c = 0; c < 8; c++) {
                int ci = c * 256 + h;
                int m = ci >> 4, qq = ci & 15;
                int e = ee0 + m;
                float4 v = {0.f, 0.f, 0.f, 0.f};
                if (e < E) v = ef4[(size_t)e * 16 + qq];
                pf[c] = v;
            }
            {
                int e = ee0 + (h & 127);
                if (e < E) pidx = (h < 128) ? idx1[e] : idx2[e];
            }
        }

        // ---- GEMM1: h = A1 @ W1^T (K=64) ----
        float acc[2][8][4];
        zero8(acc);
        wgemm_sw64<64, 128, 128>(A1u, arow, ak, W1u, brow0, bk, acc);

        // ---- epilogue 1: A2 = bf16(sp(h + b1)), swizzled ----
        #pragma unroll
        for (int mt = 0; mt < 2; mt++) {
            int r = mw * 32 + mt * 16 + g;
            #pragma unroll
            for (int nt = 0; nt < 8; nt++) {
                int c0 = nw * 64 + nt * 8 + 2 * q;
                float2 bb = *(const float2*)(b1s + c0);
                uint32_t lo = pack_bf(sp_fast(acc[mt][nt][0] + bb.x), sp_fast(acc[mt][nt][1] + bb.y));
                uint32_t hi = pack_bf(sp_fast(acc[mt][nt][2] + bb.x), sp_fast(acc[mt][nt][3] + bb.y));
                int chunk = c0 >> 3, inner = (c0 & 7) * 2;
                *(uint32_t*)(hb + HA2 + swz2(r, chunk, 256) + inner) = lo;
                *(uint32_t*)(hb + HA2 + swz2(r + 8, chunk, 256) + inner) = hi;
            }
        }
        barx(barid);   // barA: A1/idx/P reads of prior phases complete; A2 ready

        // ---- store next tile's A1 + indices (parity buffer) — overlaps GEMM2 ----
        if (have_next) {
            #pragma unroll
            for (int c = 0; c < 8; c++) {
                int ci = c * 256 + h;
                int m = ci >> 4, qq = ci & 15;
                uint2 pv = {pack_bf(pf[c].x, pf[c].y), pack_bf(pf[c].z, pf[c].w)};
                *(uint2*)(hb + HA1 + swz2(m, qq >> 1, 128) + (qq & 1) * 8) = pv;
            }
            if (h < 128) i1b[(par ^ 1) * 128 + h] = pidx;
            else         i2b[(par ^ 1) * 128 + (h - 128)] = pidx;
        }

        // ---- GEMM2 (K=128) ----
        zero8(acc);
        wgemm_sw64<128, 256, 256>(A2u, arow, ak, W2u, brow0, bk, acc);

        // ---- w = bf16(sp(acc + b2)) into P ----
        #pragma unroll
        for (int mt = 0; mt < 2; mt++) {
            int r = mw * 32 + mt * 16 + g;
            #pragma unroll
            for (int nt = 0; nt < 8; nt++) {
                int c0 = nw * 64 + nt * 8 + 2 * q;
                float2 bb = *(const float2*)(b2s + c0);
                uint32_t lo = pack_bf(sp_fast(acc[mt][nt][0] + bb.x), sp_fast(acc[mt][nt][1] + bb.y));
                uint32_t hi = pack_bf(sp_fast(acc[mt][nt][2] + bb.x), sp_fast(acc[mt][nt][3] + bb.y));
                int chunk = c0 >> 3, inner = (c0 & 7) * 2;
                *(uint32_t*)(hb + HP + swz2(r, chunk, 256) + inner) = lo;
                *(uint32_t*)(hb + HP + swz2(r + 8, chunk, 256) + inner) = hi;
            }
        }
        barx(barid);   // barB: P ready; A2 reads done; A1(t+1)/idx ready

        // ---- row pass: warp owns 16 edges; chunks of 4 (gather MLP=4) ----
        {
            const int* i1c = i1b + par * 128;
            const int* i2c = i2b + par * 128;
            #pragma unroll
            for (int j0 = 0; j0 < 16; j0 += 4) {
                uint2 wr[4];
                float4 xv[4];
                int n1[4];
                #pragma unroll
                for (int jj = 0; jj < 4; jj++) {
                    int r = wid * 16 + j0 + jj;
                    n1[jj] = i1c[r];
                    int n2 = i2c[r];
                    wr[jj] = *(const uint2*)(hb + HP + (r << 8) +
                                             ((((lane >> 1) ^ (r & 7)) & 15) << 4) + (lane & 1) * 8);
                    xv[jj] = *(const float4*)(g_x + (size_t)n2 * 128 + lane * 4);
                }
                #pragma unroll
                for (int jj = 0; jj < 4; jj++) {
                    int e = e0 + wid * 16 + j0 + jj;
                    float2 wlo = __bfloat1622float2(*(__nv_bfloat162*)&wr[jj].x);
                    float2 whi = __bfloat1622float2(*(__nv_bfloat162*)&wr[jj].y);
                    float a0 = wlo.x * xv[jj].x;
                    float a1 = wlo.y * xv[jj].y;
                    float a2 = whi.x * xv[jj].z;
                    float a3 = whi.y * xv[jj].w;
                    if (e < E) {
                        asm volatile("red.global.add.v4.f32 [%0], {%1,%2,%3,%4};"
                                     :: "l"(g_sums + (size_t)n1[jj] * 128 + lane * 4),
                                        "f"(a0), "f"(a1), "f"(a2), "f"(a3) : "memory");
                        if (lane == 0) atomicAdd(&g_cnt[n1[jj]], 1.0f);
                    }
                }
            }
        }
        par ^= 1;
        // no bar: next iteration's barA orders P/idx reads vs future writes
    }
}

// ---------------- Kernel 3: node epilogue (bf16 MMA, persistent) ----------------
#define NODE_SMEM ((128 * 136 * 3) * 2 + 128 * 4 * 3)
__global__ __launch_bounds__(256, 2) void node_mma_kernel(const float* __restrict__ node_fea,
                                                          const float* __restrict__ baw2,
                                                          const float* __restrict__ baw3,
                                                          float* __restrict__ out,
                                                          int N, int ntiles) {
    extern __shared__ char smc[];
    __nv_bfloat16* W2t = (__nv_bfloat16*)smc;
    __nv_bfloat16* W3t = W2t + 128 * 136;
    __nv_bfloat16* As  = W3t + 128 * 136;
    float* inv = (float*)(As + 128 * 136);
    float* b2s = inv + 128;
    float* b3s = b2s + 128;

    int tid = threadIdx.x, wid = tid >> 5, lane = tid & 31;
    int g = lane >> 2, q = lane & 3;
    int mw = wid & 3, nw = wid >> 2;
    int arow = (lane & 7) + ((lane >> 3) & 1) * 8, ak = lane >> 4;
    int brow = (lane & 7) + ((lane >> 4) << 3), bk = (lane >> 3) & 1;

    for (int i = tid; i < 128 * 136 * 2 / 16; i += 256) {
        ((uint4*)W2t)[i] = ((const uint4*)g_wa2b)[i];
        ((uint4*)W3t)[i] = ((const uint4*)g_wa3b)[i];
    }
    if (tid < 128) { b2s[tid] = baw2[tid]; b3s[tid] = baw3[tid]; }

    uint32_t Ab = smem_u32(As) + ((mw * 32 + arow) * 136 + ak * 8) * 2;
    uint32_t B2b = smem_u32(W2t) + ((nw * 64 + brow) * 136 + bk * 8) * 2;
    uint32_t B3b = smem_u32(W3t) + ((nw * 64 + brow) * 136 + bk * 8) * 2;

    for (int t = blockIdx.x; t < ntiles; t += gridDim.x) {
        int r0 = t * 128;
        if (tid < 128) {
            int r = r0 + tid;
            inv[tid] = (r < N) ? 1.f / fmaxf(g_cnt[r], 1.f) : 0.f;
        }
        __syncthreads();
        #pragma unroll
        for (int c = 0; c < 16; c++) {
            int ci = c * 256 + tid;
            int m = ci >> 5, qq = ci & 31;
            int r = r0 + m;
            float4 v = {0.f, 0.f, 0.f, 0.f};
            if (r < N) v = ((const float4*)g_sums)[(size_t)r * 32 + qq];
            float iv = inv[m];
            uint2 pv = {pack_bf(v.x * iv, v.y * iv), pack_bf(v.z * iv, v.w * iv)};
            *(uint2*)((char*)As + (m * 136 + qq * 4) * 2) = pv;
        }
        __syncthreads();

        float acc[2][8][4];
        zero8(acc);
        wgemm<128, 136>(Ab, B2b, acc);

        uint32_t hlo[2][8], hhi[2][8];
        #pragma unroll
        for (int mt = 0; mt < 2; mt++)
            #pragma unroll
            for (int nt = 0; nt < 8; nt++) {
                int c0 = nw * 64 + nt * 8 + 2 * q;
                float2 bb = *(const float2*)(b2s + c0);
                hlo[mt][nt] = pack_bf(sp_fast(acc[mt][nt][0] + bb.x), sp_fast(acc[mt][nt][1] + bb.y));
                hhi[mt][nt] = pack_bf(sp_fast(acc[mt][nt][2] + bb.x), sp_fast(acc[mt][nt][3] + bb.y));
            }
        __syncthreads();
        #pragma unroll
        for (int mt = 0; mt < 2; mt++) {
            int r = mw * 32 + mt * 16 + g;
            #pragma unroll
            for (int nt = 0; nt < 8; nt++) {
                int c0 = nw * 64 + nt * 8 + 2 * q;
                *(uint32_t*)((char*)As + (r * 136 + c0) * 2) = hlo[mt][nt];
                *(uint32_t*)((char*)As + ((r + 8) * 136 + c0) * 2) = hhi[mt][nt];
            }
        }
        __syncthreads();

        zero8(acc);
        wgemm<128, 136>(Ab, B3b, acc);

        #pragma unroll
        for (int mt = 0; mt < 2; mt++) {
            int rlo = r0 + mw * 32 + mt * 16 + g, rhi = rlo + 8;
            #pragma unroll
            for (int nt = 0; nt < 8; nt++) {
                int c0 = nw * 64 + nt * 8 + 2 * q;
                float2 bb = *(const float2*)(b3s + c0);
                if (rlo < N) {
                    float2 nf = *(const float2*)(node_fea + (size_t)rlo * 128 + c0);
                    *(float2*)(out + (size_t)rlo * 128 + c0) =
                        make_float2(nf.x + acc[mt][nt][0] + bb.x, nf.y + acc[mt][nt][1] + bb.y);
                }
                if (rhi < N) {
                    float2 nf = *(const float2*)(node_fea + (size_t)rhi * 128 + c0);
                    *(float2*)(out + (size_t)rhi * 128 + c0) =
                        make_float2(nf.x + acc[mt][nt][2] + bb.x, nf.y + acc[mt][nt][3] + bb.y);
                }
            }
        }
        __syncthreads();
    }
}

extern "C" void kernel_launch(void* const* d_in, const int* in_sizes, int n_in,
                              void* d_out, int out_size) {
    const float* node_fea = (const float*)d_in[0];
    const int*   idx1     = (const int*)d_in[1];
    const int*   idx2     = (const int*)d_in[2];
    const float* edge_fea = (const float*)d_in[3];
    const float* W_aw1    = (const float*)d_in[4];
    const float* W_fg1    = (const float*)d_in[5];
    const float* b_fg1    = (const float*)d_in[6];
    const float* W_fg2    = (const float*)d_in[7];
    const float* b_fg2    = (const float*)d_in[8];
    const float* W_aw2    = (const float*)d_in[9];
    const float* b_aw2    = (const float*)d_in[10];
    const float* W_aw3    = (const float*)d_in[11];
    const float* b_aw3    = (const float*)d_in[12];

    int N = in_sizes[0] / 128;
    int E = in_sizes[1];
    float* out = (float*)d_out;

    void *p_sums, *p_cnt;
    cudaGetSymbolAddress(&p_sums, g_sums);
    cudaGetSymbolAddress(&p_cnt, g_cnt);
    cudaMemsetAsync(p_sums, 0, (size_t)N * 128 * sizeof(float));
    cudaMemsetAsync(p_cnt, 0, (size_t)N * sizeof(float));

    cudaFuncSetAttribute(gemm_x_mma, cudaFuncAttributeMaxDynamicSharedMemorySize, XK_SMEM);
    cudaFuncSetAttribute(edge_mma_kernel, cudaFuncAttributeMaxDynamicSharedMemorySize, EDGE_SMEM);
    cudaFuncSetAttribute(node_mma_kernel, cudaFuncAttributeMaxDynamicSharedMemorySize, NODE_SMEM);

    int ntN = (N + 127) / 128;
    int ntE = (E + 127) / 128;
    int gbN = ntN < 296 ? ntN : 296;
    int gbE = (ntE + 1) / 2;
    if (gbE > 148) gbE = 148;

    prep_weights<<<64, 256>>>(W_fg1, W_fg2, W_aw1, W_aw2, W_aw3);
    dummy_kernel<<<1, 32>>>();
    gemm_x_mma<<<gbN, 256, XK_SMEM>>>(node_fea, N, ntN);
    edge_mma_kernel<<<gbE, 512, EDGE_SMEM>>>(edge_fea, idx1, idx2, b_fg1, b_fg2, E, ntE);
    node_mma_kernel<<<gbN, 256, NODE_SMEM>>>(node_fea, b_aw2, b_aw3, out, N, ntN);
}

// round 13
// speedup vs baseline: 1.0579x; 1.0579x over previous
#include <cuda_runtime.h>
#include <cuda_bf16.h>
#include <math.h>
#include <stdint.h>

typedef unsigned long long u64;

#define NMAX 50000
#define EMAX 640000

__device__ float g_x[(size_t)NMAX * 128];
__device__ float g_sums[(size_t)NMAX * 128];
__device__ float g_cnt[NMAX];
__device__ __align__(16) char g_w1s[128 * 128];   // W_fg1^T, K=64, 128B/row, swizzled
__device__ __align__(16) char g_w2s[128 * 256];   // W_fg2^T, K=128, 256B/row, swizzled
__device__ __align__(16) __nv_bfloat16 g_wa1b[128 * 136];
__device__ __align__(16) __nv_bfloat16 g_wa2b[128 * 136];
__device__ __align__(16) __nv_bfloat16 g_wa3b[128 * 136];

__device__ __forceinline__ float sp_fast(float x) {
    float t = __expf(-fabsf(x));
    return fmaxf(x, 0.f) + __logf(1.f + t) - 0.69314718055994531f;
}
__device__ __forceinline__ uint32_t smem_u32(const void* p) {
    uint32_t a;
    asm("{ .reg .u64 t; cvta.to.shared.u64 t, %1; cvt.u32.u64 %0, t; }" : "=r"(a) : "l"(p));
    return a;
}
__device__ __forceinline__ void ldsm4(uint32_t& r0, uint32_t& r1, uint32_t& r2, uint32_t& r3, uint32_t addr) {
    asm volatile("ldmatrix.sync.aligned.m8n8.x4.shared.b16 {%0,%1,%2,%3}, [%4];"
                 : "=r"(r0), "=r"(r1), "=r"(r2), "=r"(r3) : "r"(addr));
}
__device__ __forceinline__ void mma16(float d[4], const uint32_t a[4], uint32_t b0, uint32_t b1) {
    asm("mma.sync.aligned.m16n8k16.row.col.f32.bf16.bf16.f32 "
        "{%0,%1,%2,%3}, {%4,%5,%6,%7}, {%8,%9}, {%0,%1,%2,%3};"
        : "+f"(d[0]), "+f"(d[1]), "+f"(d[2]), "+f"(d[3])
        : "r"(a[0]), "r"(a[1]), "r"(a[2]), "r"(a[3]), "r"(b0), "r"(b1));
}
__device__ __forceinline__ uint32_t pack_bf(float lo, float hi) {
    __nv_bfloat162 p = __floats2bfloat162_rn(lo, hi);
    return *(uint32_t*)&p;
}
__device__ __forceinline__ uint32_t swz2(int row, int chunk, int RB) {
    return (uint32_t)(row * RB + (((chunk ^ (row & 7)) & (RB / 16 - 1)) << 4));
}

// ---- swizzled warp GEMM, 32(m) x 32(n) warp tile (edge kernel) ----
template<int K, int RB>
__device__ __forceinline__ void wgemm_sw(uint32_t Au, int arow, int ak,
                                         uint32_t Bu, int brow0, int bk,
                                         float acc[2][4][4]) {
    #pragma unroll
    for (int kk = 0; kk < K; kk += 16) {
        int kc = kk >> 3;
        uint32_t a[2][4];
        #pragma unroll
        for (int mt = 0; mt < 2; mt++)
            ldsm4(a[mt][0], a[mt][1], a[mt][2], a[mt][3], Au + swz2(arow + mt * 16, kc + ak, RB));
        #pragma unroll
        for (int p = 0; p < 2; p++) {
            uint32_t b0, b1, b2, b3;
            ldsm4(b0, b1, b2, b3, Bu + swz2(brow0 + p * 16, kc + bk, RB));
            mma16(acc[0][2 * p], a[0], b0, b1);
            mma16(acc[1][2 * p], a[1], b0, b1);
            mma16(acc[0][2 * p + 1], a[0], b2, b3);
            mma16(acc[1][2 * p + 1], a[1], b2, b3);
        }
    }
}

__device__ __forceinline__ void zero8(float acc[2][8][4]) {
    #pragma unroll
    for (int a = 0; a < 2; a++)
        #pragma unroll
        for (int b = 0; b < 8; b++)
            #pragma unroll
            for (int c = 0; c < 4; c++) acc[a][b][c] = 0.f;
}
// ---- padded non-swizzled warp GEMM (node / x kernels), 32x64 tile ----
template<int K, int S>
__device__ __forceinline__ void wgemm(uint32_t Abase, uint32_t Bbase, float acc[2][8][4]) {
    #pragma unroll
    for (int kk = 0; kk < K; kk += 16) {
        uint32_t a[2][4];
        #pragma unroll
        for (int mt = 0; mt < 2; mt++)
            ldsm4(a[mt][0], a[mt][1], a[mt][2], a[mt][3], Abase + (mt * 16 * S + kk) * 2);
        #pragma unroll
        for (int p = 0; p < 4; p++) {
            uint32_t b0, b1, b2, b3;
            ldsm4(b0, b1, b2, b3, Bbase + (p * 16 * S + kk) * 2);
            mma16(acc[0][2 * p], a[0], b0, b1);
            mma16(acc[1][2 * p], a[1], b0, b1);
            mma16(acc[0][2 * p + 1], a[0], b2, b3);
            mma16(acc[1][2 * p + 1], a[1], b2, b3);
        }
    }
}

__global__ void prep_weights(const float* __restrict__ W1, const float* __restrict__ W2,
                             const float* __restrict__ Wa1, const float* __restrict__ Wa2,
                             const float* __restrict__ Wa3) {
    int t = blockIdx.x * blockDim.x + threadIdx.x;
    int stride = blockDim.x * gridDim.x;
    for (int i = t; i < 64 * 128; i += stride) {
        int k = i >> 7, n = i & 127;
        *(__nv_bfloat16*)(g_w1s + swz2(n, k >> 3, 128) + (k & 7) * 2) = __float2bfloat16(W1[i]);
    }
    for (int i = t; i < 128 * 128; i += stride) {
        int k = i >> 7, n = i & 127;
        *(__nv_bfloat16*)(g_w2s + swz2(n, k >> 3, 256) + (k & 7) * 2) = __float2bfloat16(W2[i]);
        g_wa1b[n * 136 + k] = __float2bfloat16(Wa1[i]);
        g_wa2b[n * 136 + k] = __float2bfloat16(Wa2[i]);
        g_wa3b[n * 136 + k] = __float2bfloat16(Wa3[i]);
    }
}

__global__ void dummy_kernel() {}

#define XK_SMEM ((128 * 136 * 2) * 2)
__global__ __launch_bounds__(256, 2) void gemm_x_mma(const float* __restrict__ A,
                                                     int N, int ntiles) {
    extern __shared__ char smc[];
    __nv_bfloat16* Wt = (__nv_bfloat16*)smc;
    __nv_bfloat16* As = Wt + 128 * 136;
    int tid = threadIdx.x, wid = tid >> 5, lane = tid & 31;
    int g = lane >> 2, q = lane & 3;
    int mw = wid & 3, nw = wid >> 2;
    int arow = (lane & 7) + ((lane >> 3) & 1) * 8, ak = lane >> 4;
    int brow = (lane & 7) + ((lane >> 4) << 3), bk = (lane >> 3) & 1;

    for (int i = tid; i < 128 * 136 * 2 / 16; i += 256) ((uint4*)Wt)[i] = ((const uint4*)g_wa1b)[i];
    uint32_t Ab = smem_u32(As) + ((mw * 32 + arow) * 136 + ak * 8) * 2;
    uint32_t Bb = smem_u32(Wt) + ((nw * 64 + brow) * 136 + bk * 8) * 2;

    for (int t = blockIdx.x; t < ntiles; t += gridDim.x) {
        int r0 = t * 128;
        #pragma unroll
        for (int c = 0; c < 16; c++) {
            int ci = c * 256 + tid;
            int m = ci >> 5, qq = ci & 31;
            int r = r0 + m;
            float4 v = {0.f, 0.f, 0.f, 0.f};
            if (r < N) v = ((const float4*)A)[(size_t)r * 32 + qq];
            uint2 pv = {pack_bf(v.x, v.y), pack_bf(v.z, v.w)};
            *(uint2*)((char*)As + (m * 136 + qq * 4) * 2) = pv;
        }
        __syncthreads();
        float acc[2][8][4];
        zero8(acc);
        wgemm<128, 136>(Ab, Bb, acc);
        #pragma unroll
        for (int mt = 0; mt < 2; mt++) {
            int rlo = r0 + mw * 32 + mt * 16 + g, rhi = rlo + 8;
            #pragma unroll
            for (int nt = 0; nt < 8; nt++) {
                int c0 = nw * 64 + nt * 8 + 2 * q;
                if (rlo < N) *(float2*)(g_x + (size_t)rlo * 128 + c0) = make_float2(acc[mt][nt][0], acc[mt][nt][1]);
                if (rhi < N) *(float2*)(g_x + (size_t)rhi * 128 + c0) = make_float2(acc[mt][nt][2], acc[mt][nt][3]);
            }
        }
        __syncthreads();
    }
}

// ---------------- Kernel 2: persistent bf16-MMA edge pipeline (R11 structure) ----------------
// smem: W1 16K @0, W2 32K @16384, A1 8K @49152, A2 16K @57344, P 32K @73728
//       b1s @106496, b2s @107008, i1s @107520, i2s @107776   total 108032
#define EW1 0
#define EW2 16384
#define EA1 49152
#define EA2 57344
#define EP  73728
#define EB1 106496
#define EB2 107008
#define EI1 107520
#define EI2 107776
#define EDGE_SMEM 108032

__global__ __launch_bounds__(256, 2) void edge_mma_kernel(const float* __restrict__ ef,
                                                          const int* __restrict__ idx1,
                                                          const int* __restrict__ idx2,
                                                          const float* __restrict__ b1,
                                                          const float* __restrict__ b2,
                                                          int E, int ntiles) {
    extern __shared__ char smc[];
    float* b1s = (float*)(smc + EB1);
    float* b2s = (float*)(smc + EB2);
    int* i1s = (int*)(smc + EI1);
    int* i2s = (int*)(smc + EI2);

    int tid = threadIdx.x, wid = tid >> 5, lane = tid & 31;
    int g = lane >> 2, q = lane & 3;
    int mw = wid >> 2, nw = wid & 3;          // 2(m) x 4(n) warp grid, 32x32 tiles
    int arow_l = (lane & 7) + ((lane >> 3) & 1) * 8, ak = lane >> 4;
    int brow_l = (lane & 7) + ((lane >> 4) << 3), bk = (lane >> 3) & 1;
    const float4* ef4 = (const float4*)ef;

    uint32_t sb = smem_u32(smc);
    uint32_t W1u = sb + EW1, W2u = sb + EW2, A1u = sb + EA1, A2u = sb + EA2;

    for (int i = tid; i < 16384 / 16; i += 256) ((uint4*)(smc + EW1))[i] = ((const uint4*)g_w1s)[i];
    for (int i = tid; i < 32768 / 16; i += 256) ((uint4*)(smc + EW2))[i] = ((const uint4*)g_w2s)[i];
    if (tid < 128) { b1s[tid] = b1[tid]; b2s[tid] = b2[tid]; }

    int arow = mw * 32 + arow_l;
    int brow0 = nw * 32 + brow_l;

    int t = blockIdx.x;
    if (t < ntiles) {
        int e0 = t * 64;
        #pragma unroll
        for (int c = 0; c < 4; c++) {
            int ci = c * 256 + tid;
            int m = ci >> 4, qq = ci & 15;
            int e = e0 + m;
            float4 v = {0.f, 0.f, 0.f, 0.f};
            if (e < E) v = ef4[(size_t)e * 16 + qq];
            uint2 pv = {pack_bf(v.x, v.y), pack_bf(v.z, v.w)};
            *(uint2*)(smc + EA1 + swz2(m, qq >> 1, 128) + (qq & 1) * 8) = pv;
        }
        if (tid < 128) {
            int e = e0 + (tid & 63);
            int v = (e < E) ? ((tid < 64) ? idx1[e] : idx2[e]) : 0;
            if (tid < 64) i1s[tid] = v; else i2s[tid - 64] = v;
        }
    }
    __syncthreads();

    for (; t < ntiles; t += gridDim.x) {
        int e0 = t * 64;
        int tn = t + gridDim.x;
        bool have_next = tn < ntiles;

        // register-prefetch next tile's edge features + indices
        float4 pf[4];
        int pidx = 0;
        if (have_next) {
            int ee0 = tn * 64;
            #pragma unroll
            for (int c = 0; c < 4; c++) {
                int ci = c * 256 + tid;
                int m = ci >> 4, qq = ci & 15;
                int e = ee0 + m;
                float4 v = {0.f, 0.f, 0.f, 0.f};
                if (e < E) v = ef4[(size_t)e * 16 + qq];
                pf[c] = v;
            }
            if (tid < 128) {
                int e = ee0 + (tid & 63);
                if (e < E) pidx = (tid < 64) ? idx1[e] : idx2[e];
            }
        }

        // current tile indices + row-coalesced x-gathers (land during GEMMs)
        float4 xg[8];
        int n1r[8];
        #pragma unroll
        for (int j = 0; j < 8; j++) {
            int r = wid * 8 + j;
            int n2 = i2s[r];
            n1r[j] = i1s[r];
            xg[j] = *(const float4*)(g_x + (size_t)n2 * 128 + lane * 4);
        }

        // ---- GEMM1: h = A1 @ W1^T (K=64) ----
        float acc[2][4][4];
        #pragma unroll
        for (int a = 0; a < 2; a++)
            #pragma unroll
            for (int b = 0; b < 4; b++)
                #pragma unroll
                for (int c = 0; c < 4; c++) acc[a][b][c] = 0.f;
        wgemm_sw<64, 128>(A1u, arow, ak, W1u, brow0, bk, acc);

        // ---- epilogue 1: A2 = bf16(sp(h + b1)) ----
        #pragma unroll
        for (int mt = 0; mt < 2; mt++) {
            int r = mw * 32 + mt * 16 + g;
            #pragma unroll
            for (int nt = 0; nt < 4; nt++) {
                int c0 = nw * 32 + nt * 8 + 2 * q;
                float2 bb = *(const float2*)(b1s + c0);
                uint32_t lo = pack_bf(sp_fast(acc[mt][nt][0] + bb.x), sp_fast(acc[mt][nt][1] + bb.y));
                uint32_t hi = pack_bf(sp_fast(acc[mt][nt][2] + bb.x), sp_fast(acc[mt][nt][3] + bb.y));
                int chunk = c0 >> 3, inner = (c0 & 7) * 2;
                *(uint32_t*)(smc + EA2 + swz2(r, chunk, 256) + inner) = lo;
                *(uint32_t*)(smc + EA2 + swz2(r + 8, chunk, 256) + inner) = hi;
            }
        }
        __syncthreads();   // syncA

        // store next tile's A1 + indices (overlaps GEMM2)
        if (have_next) {
            #pragma unroll
            for (int c = 0; c < 4; c++) {
                int ci = c * 256 + tid;
                int m = ci >> 4, qq = ci & 15;
                uint2 pv = {pack_bf(pf[c].x, pf[c].y), pack_bf(pf[c].z, pf[c].w)};
                *(uint2*)(smc + EA1 + swz2(m, qq >> 1, 128) + (qq & 1) * 8) = pv;
            }
            if (tid < 128) {
                if (tid < 64) i1s[tid] = pidx; else i2s[tid - 64] = pidx;
            }
        }

        // ---- GEMM2: P = A2 @ W2^T (K=128) ----
        #pragma unroll
        for (int a = 0; a < 2; a++)
            #pragma unroll
            for (int b = 0; b < 4; b++)
                #pragma unroll
                for (int c = 0; c < 4; c++) acc[a][b][c] = 0.f;
        wgemm_sw<128, 256>(A2u, arow, ak, W2u, brow0, bk, acc);

        // ---- dump raw GEMM2 acc into P (f32, xor-swizzled 512B rows) ----
        #pragma unroll
        for (int mt = 0; mt < 2; mt++) {
            int rlo = mw * 32 + mt * 16 + g, rhi = rlo + 8;
            #pragma unroll
            for (int nt = 0; nt < 4; nt++) {
                int c0 = nw * 32 + nt * 8 + 2 * q;
                int chunk = c0 >> 2, inner = (c0 & 3) * 4;
                *(float2*)(smc + EP + (rlo << 9) + (((chunk ^ (rlo & 7)) & 31) << 4) + inner)
                    = make_float2(acc[mt][nt][0], acc[mt][nt][1]);
                *(float2*)(smc + EP + (rhi << 9) + (((chunk ^ (rhi & 7)) & 31) << 4) + inner)
                    = make_float2(acc[mt][nt][2], acc[mt][nt][3]);
            }
        }
        __syncthreads();   // syncB

        // ---- row pass: warp owns 8 edges; full-row coalesced sp + gather-mul + red.v4 ----
        {
            float4 b2v = *(const float4*)(b2s + lane * 4);
            #pragma unroll
            for (int j = 0; j < 8; j++) {
                int r = wid * 8 + j;
                int e = e0 + r;
                float4 p = *(const float4*)(smc + EP + (r << 9) + (((lane ^ (r & 7)) & 31) << 4));
                float4 xv = xg[j];
                float a0 = sp_fast(p.x + b2v.x) * xv.x;
                float a1 = sp_fast(p.y + b2v.y) * xv.y;
                float a2 = sp_fast(p.z + b2v.z) * xv.z;
                float a3 = sp_fast(p.w + b2v.w) * xv.w;
                if (e < E) {
                    asm volatile("red.global.add.v4.f32 [%0], {%1,%2,%3,%4};"
                                 :: "l"(g_sums + (size_t)n1r[j] * 128 + lane * 4),
                                    "f"(a0), "f"(a1), "f"(a2), "f"(a3) : "memory");
                    if (lane == 0) atomicAdd(&g_cnt[n1r[j]], 1.0f);
                }
            }
        }
        // no sync: next iteration's syncA separates P reads from next P writes
    }
}

// ---------------- Kernel 3: node epilogue (bf16 MMA, persistent, 4 syncs) ----------------
#define NODE_SMEM ((128 * 136 * 3) * 2 + 128 * 4 * 2)
__global__ __launch_bounds__(256, 2) void node_mma_kernel(const float* __restrict__ node_fea,
                                                          const float* __restrict__ baw2,
                                                          const float* __restrict__ baw3,
                                                          float* __restrict__ out,
                                                          int N, int ntiles) {
    extern __shared__ char smc[];
    __nv_bfloat16* W2t = (__nv_bfloat16*)smc;
    __nv_bfloat16* W3t = W2t + 128 * 136;
    __nv_bfloat16* As  = W3t + 128 * 136;
    float* b2s = (float*)(As + 128 * 136);
    float* b3s = b2s + 128;

    int tid = threadIdx.x, wid = tid >> 5, lane = tid & 31;
    int g = lane >> 2, q = lane & 3;
    int mw = wid & 3, nw = wid >> 2;
    int arow = (lane & 7) + ((lane >> 3) & 1) * 8, ak = lane >> 4;
    int brow = (lane & 7) + ((lane >> 4) << 3), bk = (lane >> 3) & 1;

    for (int i = tid; i < 128 * 136 * 2 / 16; i += 256) {
        ((uint4*)W2t)[i] = ((const uint4*)g_wa2b)[i];
        ((uint4*)W3t)[i] = ((const uint4*)g_wa3b)[i];
    }
    if (tid < 128) { b2s[tid] = baw2[tid]; b3s[tid] = baw3[tid]; }

    uint32_t Ab = smem_u32(As) + ((mw * 32 + arow) * 136 + ak * 8) * 2;
    uint32_t B2b = smem_u32(W2t) + ((nw * 64 + brow) * 136 + bk * 8) * 2;
    uint32_t B3b = smem_u32(W3t) + ((nw * 64 + brow) * 136 + bk * 8) * 2;

    for (int t = blockIdx.x; t < ntiles; t += gridDim.x) {
        int r0 = t * 128;
        // load sums tile, divide by cnt (per-thread __ldg broadcast — no inv[] staging)
        #pragma unroll
        for (int c = 0; c < 16; c++) {
            int ci = c * 256 + tid;
            int m = ci >> 5, qq = ci & 31;
            int r = r0 + m;
            float4 v = {0.f, 0.f, 0.f, 0.f};
            float iv = 0.f;
            if (r < N) {
                v = ((const float4*)g_sums)[(size_t)r * 32 + qq];
                iv = __frcp_rn(fmaxf(__ldg(&g_cnt[r]), 1.f));
            }
            uint2 pv = {pack_bf(v.x * iv, v.y * iv), pack_bf(v.z * iv, v.w * iv)};
            *(uint2*)((char*)As + (m * 136 + qq * 4) * 2) = pv;
        }
        __syncthreads();   // sync 1

        float acc[2][8][4];
        zero8(acc);
        wgemm<128, 136>(Ab, B2b, acc);

        uint32_t hlo[2][8], hhi[2][8];
        #pragma unroll
        for (int mt = 0; mt < 2; mt++)
            #pragma unroll
            for (int nt = 0; nt < 8; nt++) {
                int c0 = nw * 64 + nt * 8 + 2 * q;
                float2 bb = *(const float2*)(b2s + c0);
                hlo[mt][nt] = pack_bf(sp_fast(acc[mt][nt][0] + bb.x), sp_fast(acc[mt][nt][1] + bb.y));
                hhi[mt][nt] = pack_bf(sp_fast(acc[mt][nt][2] + bb.x), sp_fast(acc[mt][nt][3] + bb.y));
            }
        __syncthreads();   // sync 2: GEMM1 reads of As done
        #pragma unroll
        for (int mt = 0; mt < 2; mt++) {
            int r = mw * 32 + mt * 16 + g;
            #pragma unroll
            for (int nt = 0; nt < 8; nt++) {
                int c0 = nw * 64 + nt * 8 + 2 * q;
                *(uint32_t*)((char*)As + (r * 136 + c0) * 2) = hlo[mt][nt];
                *(uint32_t*)((char*)As + ((r + 8) * 136 + c0) * 2) = hhi[mt][nt];
            }
        }
        __syncthreads();   // sync 3: h visible

        zero8(acc);
        wgemm<128, 136>(Ab, B3b, acc);

        #pragma unroll
        for (int mt = 0; mt < 2; mt++) {
            int rlo = r0 + mw * 32 + mt * 16 + g, rhi = rlo + 8;
            #pragma unroll
            for (int nt = 0; nt < 8; nt++) {
                int c0 = nw * 64 + nt * 8 + 2 * q;
                float2 bb = *(const float2*)(b3s + c0);
                if (rlo < N) {
                    float2 nf = *(const float2*)(node_fea + (size_t)rlo * 128 + c0);
                    *(float2*)(out + (size_t)rlo * 128 + c0) =
                        make_float2(nf.x + acc[mt][nt][0] + bb.x, nf.y + acc[mt][nt][1] + bb.y);
                }
                if (rhi < N) {
                    float2 nf = *(const float2*)(node_fea + (size_t)rhi * 128 + c0);
                    *(float2*)(out + (size_t)rhi * 128 + c0) =
                        make_float2(nf.x + acc[mt][nt][2] + bb.x, nf.y + acc[mt][nt][3] + bb.y);
                }
            }
        }
        __syncthreads();   // sync 4: As reads done before next tile's writes
    }
}

extern "C" void kernel_launch(void* const* d_in, const int* in_sizes, int n_in,
                              void* d_out, int out_size) {
    const float* node_fea = (const float*)d_in[0];
    const int*   idx1     = (const int*)d_in[1];
    const int*   idx2     = (const int*)d_in[2];
    const float* edge_fea = (const float*)d_in[3];
    const float* W_aw1    = (const float*)d_in[4];
    const float* W_fg1    = (const float*)d_in[5];
    const float* b_fg1    = (const float*)d_in[6];
    const float* W_fg2    = (const float*)d_in[7];
    const float* b_fg2    = (const float*)d_in[8];
    const float* W_aw2    = (const float*)d_in[9];
    const float* b_aw2    = (const float*)d_in[10];
    const float* W_aw3    = (const float*)d_in[11];
    const float* b_aw3    = (const float*)d_in[12];

    int N = in_sizes[0] / 128;
    int E = in_sizes[1];
    float* out = (float*)d_out;

    void *p_sums, *p_cnt;
    cudaGetSymbolAddress(&p_sums, g_sums);
    cudaGetSymbolAddress(&p_cnt, g_cnt);
    cudaMemsetAsync(p_sums, 0, (size_t)N * 128 * sizeof(float));
    cudaMemsetAsync(p_cnt, 0, (size_t)N * sizeof(float));

    cudaFuncSetAttribute(gemm_x_mma, cudaFuncAttributeMaxDynamicSharedMemorySize, XK_SMEM);
    cudaFuncSetAttribute(edge_mma_kernel, cudaFuncAttributeMaxDynamicSharedMemorySize, EDGE_SMEM);
    cudaFuncSetAttribute(node_mma_kernel, cudaFuncAttributeMaxDynamicSharedMemorySize, NODE_SMEM);

    int ntN = (N + 127) / 128;
    int ntE = (E + 63) / 64;
    int gbN = ntN < 296 ? ntN : 296;
    int gbE = ntE < 296 ? ntE : 296;

    prep_weights<<<64, 256>>>(W_fg1, W_fg2, W_aw1, W_aw2, W_aw3);
    dummy_kernel<<<1, 32>>>();
    gemm_x_mma<<<gbN, 256, XK_SMEM>>>(node_fea, N, ntN);
    edge_mma_kernel<<<gbE, 256, EDGE_SMEM>>>(edge_fea, idx1, idx2, b_fg1, b_fg2, E, ntE);
    node_mma_kernel<<<gbN, 256, NODE_SMEM>>>(node_fea, b_aw2, b_aw3, out, N, ntN);
}

// round 14
// speedup vs baseline: 1.0851x; 1.0257x over previous
#include <cuda_runtime.h>
#include <cuda_bf16.h>
#include <math.h>
#include <stdint.h>

typedef unsigned long long u64;

#define NMAX 50000
#define EMAX 640000

__device__ float g_x[(size_t)NMAX * 128];
__device__ float g_sums[(size_t)NMAX * 128];
__device__ float g_cnt[NMAX];
__device__ __align__(16) char g_w1s[128 * 128];   // W_fg1^T, K=64, 128B/row, swizzled
__device__ __align__(16) char g_w2s[128 * 256];   // W_fg2^T, K=128, 256B/row, swizzled
__device__ __align__(16) __nv_bfloat16 g_wa1b[128 * 136];
__device__ __align__(16) __nv_bfloat16 g_wa2b[128 * 136];
__device__ __align__(16) __nv_bfloat16 g_wa3b[128 * 136];

__device__ __forceinline__ float sp_fast(float x) {
    float t = __expf(-fabsf(x));
    return fmaxf(x, 0.f) + __logf(1.f + t) - 0.69314718055994531f;
}
__device__ __forceinline__ uint32_t smem_u32(const void* p) {
    uint32_t a;
    asm("{ .reg .u64 t; cvta.to.shared.u64 t, %1; cvt.u32.u64 %0, t; }" : "=r"(a) : "l"(p));
    return a;
}
__device__ __forceinline__ void ldsm4(uint32_t& r0, uint32_t& r1, uint32_t& r2, uint32_t& r3, uint32_t addr) {
    asm volatile("ldmatrix.sync.aligned.m8n8.x4.shared.b16 {%0,%1,%2,%3}, [%4];"
                 : "=r"(r0), "=r"(r1), "=r"(r2), "=r"(r3) : "r"(addr));
}
__device__ __forceinline__ void mma16(float d[4], const uint32_t a[4], uint32_t b0, uint32_t b1) {
    asm("mma.sync.aligned.m16n8k16.row.col.f32.bf16.bf16.f32 "
        "{%0,%1,%2,%3}, {%4,%5,%6,%7}, {%8,%9}, {%0,%1,%2,%3};"
        : "+f"(d[0]), "+f"(d[1]), "+f"(d[2]), "+f"(d[3])
        : "r"(a[0]), "r"(a[1]), "r"(a[2]), "r"(a[3]), "r"(b0), "r"(b1));
}
__device__ __forceinline__ uint32_t pack_bf(float lo, float hi) {
    __nv_bfloat162 p = __floats2bfloat162_rn(lo, hi);
    return *(uint32_t*)&p;
}
__device__ __forceinline__ uint32_t swz2(int row, int chunk, int RB) {
    return (uint32_t)(row * RB + (((chunk ^ (row & 7)) & (RB / 16 - 1)) << 4));
}

// ---- swizzled warp GEMM, 32(m) x 32(n) warp tile (edge kernel) ----
template<int K, int RB>
__device__ __forceinline__ void wgemm_sw(uint32_t Au, int arow, int ak,
                                         uint32_t Bu, int brow0, int bk,
                                         float acc[2][4][4]) {
    #pragma unroll
    for (int kk = 0; kk < K; kk += 16) {
        int kc = kk >> 3;
        uint32_t a[2][4];
        #pragma unroll
        for (int mt = 0; mt < 2; mt++)
            ldsm4(a[mt][0], a[mt][1], a[mt][2], a[mt][3], Au + swz2(arow + mt * 16, kc + ak, RB));
        #pragma unroll
        for (int p = 0; p < 2; p++) {
            uint32_t b0, b1, b2, b3;
            ldsm4(b0, b1, b2, b3, Bu + swz2(brow0 + p * 16, kc + bk, RB));
            mma16(acc[0][2 * p], a[0], b0, b1);
            mma16(acc[1][2 * p], a[1], b0, b1);
            mma16(acc[0][2 * p + 1], a[0], b2, b3);
            mma16(acc[1][2 * p + 1], a[1], b2, b3);
        }
    }
}

__device__ __forceinline__ void zero8(float acc[2][8][4]) {
    #pragma unroll
    for (int a = 0; a < 2; a++)
        #pragma unroll
        for (int b = 0; b < 8; b++)
            #pragma unroll
            for (int c = 0; c < 4; c++) acc[a][b][c] = 0.f;
}
// ---- padded non-swizzled warp GEMM (node / x kernels), 32x64 tile ----
template<int K, int S>
__device__ __forceinline__ void wgemm(uint32_t Abase, uint32_t Bbase, float acc[2][8][4]) {
    #pragma unroll
    for (int kk = 0; kk < K; kk += 16) {
        uint32_t a[2][4];
        #pragma unroll
        for (int mt = 0; mt < 2; mt++)
            ldsm4(a[mt][0], a[mt][1], a[mt][2], a[mt][3], Abase + (mt * 16 * S + kk) * 2);
        #pragma unroll
        for (int p = 0; p < 4; p++) {
            uint32_t b0, b1, b2, b3;
            ldsm4(b0, b1, b2, b3, Bbase + (p * 16 * S + kk) * 2);
            mma16(acc[0][2 * p], a[0], b0, b1);
            mma16(acc[1][2 * p], a[1], b0, b1);
            mma16(acc[0][2 * p + 1], a[0], b2, b3);
            mma16(acc[1][2 * p + 1], a[1], b2, b3);
        }
    }
}

__global__ void prep_weights(const float* __restrict__ W1, const float* __restrict__ W2,
                             const float* __restrict__ Wa1, const float* __restrict__ Wa2,
                             const float* __restrict__ Wa3) {
    int t = blockIdx.x * blockDim.x + threadIdx.x;
    int stride = blockDim.x * gridDim.x;
    for (int i = t; i < 64 * 128; i += stride) {
        int k = i >> 7, n = i & 127;
        *(__nv_bfloat16*)(g_w1s + swz2(n, k >> 3, 128) + (k & 7) * 2) = __float2bfloat16(W1[i]);
    }
    for (int i = t; i < 128 * 128; i += stride) {
        int k = i >> 7, n = i & 127;
        *(__nv_bfloat16*)(g_w2s + swz2(n, k >> 3, 256) + (k & 7) * 2) = __float2bfloat16(W2[i]);
        g_wa1b[n * 136 + k] = __float2bfloat16(Wa1[i]);
        g_wa2b[n * 136 + k] = __float2bfloat16(Wa2[i]);
        g_wa3b[n * 136 + k] = __float2bfloat16(Wa3[i]);
    }
}

#define XK_SMEM ((128 * 136 * 2) * 2)
__global__ __launch_bounds__(256, 2) void gemm_x_mma(const float* __restrict__ A,
                                                     int N, int ntiles) {
    extern __shared__ char smc[];
    __nv_bfloat16* Wt = (__nv_bfloat16*)smc;
    __nv_bfloat16* As = Wt + 128 * 136;
    int tid = threadIdx.x, wid = tid >> 5, lane = tid & 31;
    int g = lane >> 2, q = lane & 3;
    int mw = wid & 3, nw = wid >> 2;
    int arow = (lane & 7) + ((lane >> 3) & 1) * 8, ak = lane >> 4;
    int brow = (lane & 7) + ((lane >> 4) << 3), bk = (lane >> 3) & 1;

    for (int i = tid; i < 128 * 136 * 2 / 16; i += 256) ((uint4*)Wt)[i] = ((const uint4*)g_wa1b)[i];
    uint32_t Ab = smem_u32(As) + ((mw * 32 + arow) * 136 + ak * 8) * 2;
    uint32_t Bb = smem_u32(Wt) + ((nw * 64 + brow) * 136 + bk * 8) * 2;

    for (int t = blockIdx.x; t < ntiles; t += gridDim.x) {
        int r0 = t * 128;
        #pragma unroll
        for (int c = 0; c < 16; c++) {
            int ci = c * 256 + tid;
            int m = ci >> 5, qq = ci & 31;
            int r = r0 + m;
            float4 v = {0.f, 0.f, 0.f, 0.f};
            if (r < N) v = ((const float4*)A)[(size_t)r * 32 + qq];
            uint2 pv = {pack_bf(v.x, v.y), pack_bf(v.z, v.w)};
            *(uint2*)((char*)As + (m * 136 + qq * 4) * 2) = pv;
        }
        __syncthreads();
        float acc[2][8][4];
        zero8(acc);
        wgemm<128, 136>(Ab, Bb, acc);
        #pragma unroll
        for (int mt = 0; mt < 2; mt++) {
            int rlo = r0 + mw * 32 + mt * 16 + g, rhi = rlo + 8;
            #pragma unroll
            for (int nt = 0; nt < 8; nt++) {
                int c0 = nw * 64 + nt * 8 + 2 * q;
                if (rlo < N) *(float2*)(g_x + (size_t)rlo * 128 + c0) = make_float2(acc[mt][nt][0], acc[mt][nt][1]);
                if (rhi < N) *(float2*)(g_x + (size_t)rhi * 128 + c0) = make_float2(acc[mt][nt][2], acc[mt][nt][3]);
            }
        }
        __syncthreads();
    }
}

// ---------------- Kernel 2: persistent bf16-MMA edge pipeline (R11 structure) ----------------
#define EW1 0
#define EW2 16384
#define EA1 49152
#define EA2 57344
#define EP  73728
#define EB1 106496
#define EB2 107008
#define EI1 107520
#define EI2 107776
#define EDGE_SMEM 108032

__global__ __launch_bounds__(256, 2) void edge_mma_kernel(const float* __restrict__ ef,
                                                          const int* __restrict__ idx1,
                                                          const int* __restrict__ idx2,
                                                          const float* __restrict__ b1,
                                                          const float* __restrict__ b2,
                                                          int E, int ntiles) {
    extern __shared__ char smc[];
    float* b1s = (float*)(smc + EB1);
    float* b2s = (float*)(smc + EB2);
    int* i1s = (int*)(smc + EI1);
    int* i2s = (int*)(smc + EI2);

    int tid = threadIdx.x, wid = tid >> 5, lane = tid & 31;
    int g = lane >> 2, q = lane & 3;
    int mw = wid >> 2, nw = wid & 3;          // 2(m) x 4(n) warp grid, 32x32 tiles
    int arow_l = (lane & 7) + ((lane >> 3) & 1) * 8, ak = lane >> 4;
    int brow_l = (lane & 7) + ((lane >> 4) << 3), bk = (lane >> 3) & 1;
    const float4* ef4 = (const float4*)ef;

    uint32_t sb = smem_u32(smc);
    uint32_t W1u = sb + EW1, W2u = sb + EW2, A1u = sb + EA1, A2u = sb + EA2;

    for (int i = tid; i < 16384 / 16; i += 256) ((uint4*)(smc + EW1))[i] = ((const uint4*)g_w1s)[i];
    for (int i = tid; i < 32768 / 16; i += 256) ((uint4*)(smc + EW2))[i] = ((const uint4*)g_w2s)[i];
    if (tid < 128) { b1s[tid] = b1[tid]; b2s[tid] = b2[tid]; }

    int arow = mw * 32 + arow_l;
    int brow0 = nw * 32 + brow_l;

    int t = blockIdx.x;
    if (t < ntiles) {
        int e0 = t * 64;
        #pragma unroll
        for (int c = 0; c < 4; c++) {
            int ci = c * 256 + tid;
            int m = ci >> 4, qq = ci & 15;
            int e = e0 + m;
            float4 v = {0.f, 0.f, 0.f, 0.f};
            if (e < E) v = ef4[(size_t)e * 16 + qq];
            uint2 pv = {pack_bf(v.x, v.y), pack_bf(v.z, v.w)};
            *(uint2*)(smc + EA1 + swz2(m, qq >> 1, 128) + (qq & 1) * 8) = pv;
        }
        if (tid < 128) {
            int e = e0 + (tid & 63);
            int v = (e < E) ? ((tid < 64) ? idx1[e] : idx2[e]) : 0;
            if (tid < 64) i1s[tid] = v; else i2s[tid - 64] = v;
        }
    }
    __syncthreads();

    for (; t < ntiles; t += gridDim.x) {
        int e0 = t * 64;
        int tn = t + gridDim.x;
        bool have_next = tn < ntiles;

        // register-prefetch next tile's edge features + indices
        float4 pf[4];
        int pidx = 0;
        if (have_next) {
            int ee0 = tn * 64;
            #pragma unroll
            for (int c = 0; c < 4; c++) {
                int ci = c * 256 + tid;
                int m = ci >> 4, qq = ci & 15;
                int e = ee0 + m;
                float4 v = {0.f, 0.f, 0.f, 0.f};
                if (e < E) v = ef4[(size_t)e * 16 + qq];
                pf[c] = v;
            }
            if (tid < 128) {
                int e = ee0 + (tid & 63);
                if (e < E) pidx = (tid < 64) ? idx1[e] : idx2[e];
            }
        }

        // current tile indices + row-coalesced x-gathers (land during GEMMs)
        float4 xg[8];
        int n1r[8];
        #pragma unroll
        for (int j = 0; j < 8; j++) {
            int r = wid * 8 + j;
            int n2 = i2s[r];
            n1r[j] = i1s[r];
            xg[j] = *(const float4*)(g_x + (size_t)n2 * 128 + lane * 4);
        }

        // ---- GEMM1: h = A1 @ W1^T (K=64) ----
        float acc[2][4][4];
        #pragma unroll
        for (int a = 0; a < 2; a++)
            #pragma unroll
            for (int b = 0; b < 4; b++)
                #pragma unroll
                for (int c = 0; c < 4; c++) acc[a][b][c] = 0.f;
        wgemm_sw<64, 128>(A1u, arow, ak, W1u, brow0, bk, acc);

        // ---- epilogue 1: A2 = bf16(sp(h + b1)) ----
        #pragma unroll
        for (int mt = 0; mt < 2; mt++) {
            int r = mw * 32 + mt * 16 + g;
            #pragma unroll
            for (int nt = 0; nt < 4; nt++) {
                int c0 = nw * 32 + nt * 8 + 2 * q;
                float2 bb = *(const float2*)(b1s + c0);
                uint32_t lo = pack_bf(sp_fast(acc[mt][nt][0] + bb.x), sp_fast(acc[mt][nt][1] + bb.y));
                uint32_t hi = pack_bf(sp_fast(acc[mt][nt][2] + bb.x), sp_fast(acc[mt][nt][3] + bb.y));
                int chunk = c0 >> 3, inner = (c0 & 7) * 2;
                *(uint32_t*)(smc + EA2 + swz2(r, chunk, 256) + inner) = lo;
                *(uint32_t*)(smc + EA2 + swz2(r + 8, chunk, 256) + inner) = hi;
            }
        }
        __syncthreads();   // syncA

        // store next tile's A1 + indices (overlaps GEMM2)
        if (have_next) {
            #pragma unroll
            for (int c = 0; c < 4; c++) {
                int ci = c * 256 + tid;
                int m = ci >> 4, qq = ci & 15;
                uint2 pv = {pack_bf(pf[c].x, pf[c].y), pack_bf(pf[c].z, pf[c].w)};
                *(uint2*)(smc + EA1 + swz2(m, qq >> 1, 128) + (qq & 1) * 8) = pv;
            }
            if (tid < 128) {
                if (tid < 64) i1s[tid] = pidx; else i2s[tid - 64] = pidx;
            }
        }

        // ---- GEMM2: P = A2 @ W2^T (K=128) ----
        #pragma unroll
        for (int a = 0; a < 2; a++)
            #pragma unroll
            for (int b = 0; b < 4; b++)
                #pragma unroll
                for (int c = 0; c < 4; c++) acc[a][b][c] = 0.f;
        wgemm_sw<128, 256>(A2u, arow, ak, W2u, brow0, bk, acc);

        // ---- dump raw GEMM2 acc into P (f32, xor-swizzled 512B rows) ----
        #pragma unroll
        for (int mt = 0; mt < 2; mt++) {
            int rlo = mw * 32 + mt * 16 + g, rhi = rlo + 8;
            #pragma unroll
            for (int nt = 0; nt < 4; nt++) {
                int c0 = nw * 32 + nt * 8 + 2 * q;
                int chunk = c0 >> 2, inner = (c0 & 3) * 4;
                *(float2*)(smc + EP + (rlo << 9) + (((chunk ^ (rlo & 7)) & 31) << 4) + inner)
                    = make_float2(acc[mt][nt][0], acc[mt][nt][1]);
                *(float2*)(smc + EP + (rhi << 9) + (((chunk ^ (rhi & 7)) & 31) << 4) + inner)
                    = make_float2(acc[mt][nt][2], acc[mt][nt][3]);
            }
        }
        __syncthreads();   // syncB

        // ---- row pass: warp owns 8 edges; full-row coalesced sp + gather-mul + red.v4 ----
        {
            float4 b2v = *(const float4*)(b2s + lane * 4);
            #pragma unroll
            for (int j = 0; j < 8; j++) {
                int r = wid * 8 + j;
                int e = e0 + r;
                float4 p = *(const float4*)(smc + EP + (r << 9) + (((lane ^ (r & 7)) & 31) << 4));
                float4 xv = xg[j];
                float a0 = sp_fast(p.x + b2v.x) * xv.x;
                float a1 = sp_fast(p.y + b2v.y) * xv.y;
                float a2 = sp_fast(p.z + b2v.z) * xv.z;
                float a3 = sp_fast(p.w + b2v.w) * xv.w;
                if (e < E) {
                    asm volatile("red.global.add.v4.f32 [%0], {%1,%2,%3,%4};"
                                 :: "l"(g_sums + (size_t)n1r[j] * 128 + lane * 4),
                                    "f"(a0), "f"(a1), "f"(a2), "f"(a3) : "memory");
                    if (lane == 0) atomicAdd(&g_cnt[n1r[j]], 1.0f);
                }
            }
        }
        // no sync: next iteration's syncA separates P reads from next P writes
    }
}

// ---------------- Kernel 3: node epilogue (bf16 MMA, persistent — R11 version) ----------------
#define NODE_SMEM ((128 * 136 * 3) * 2 + 128 * 4 * 3)
__global__ __launch_bounds__(256, 2) void node_mma_kernel(const float* __restrict__ node_fea,
                                                          const float* __restrict__ baw2,
                                                          const float* __restrict__ baw3,
                                                          float* __restrict__ out,
                                                          int N, int ntiles) {
    extern __shared__ char smc[];
    __nv_bfloat16* W2t = (__nv_bfloat16*)smc;
    __nv_bfloat16* W3t = W2t + 128 * 136;
    __nv_bfloat16* As  = W3t + 128 * 136;
    float* inv = (float*)(As + 128 * 136);
    float* b2s = inv + 128;
    float* b3s = b2s + 128;

    int tid = threadIdx.x, wid = tid >> 5, lane = tid & 31;
    int g = lane >> 2, q = lane & 3;
    int mw = wid & 3, nw = wid >> 2;
    int arow = (lane & 7) + ((lane >> 3) & 1) * 8, ak = lane >> 4;
    int brow = (lane & 7) + ((lane >> 4) << 3), bk = (lane >> 3) & 1;

    for (int i = tid; i < 128 * 136 * 2 / 16; i += 256) {
        ((uint4*)W2t)[i] = ((const uint4*)g_wa2b)[i];
        ((uint4*)W3t)[i] = ((const uint4*)g_wa3b)[i];
    }
    if (tid < 128) { b2s[tid] = baw2[tid]; b3s[tid] = baw3[tid]; }

    uint32_t Ab = smem_u32(As) + ((mw * 32 + arow) * 136 + ak * 8) * 2;
    uint32_t B2b = smem_u32(W2t) + ((nw * 64 + brow) * 136 + bk * 8) * 2;
    uint32_t B3b = smem_u32(W3t) + ((nw * 64 + brow) * 136 + bk * 8) * 2;

    for (int t = blockIdx.x; t < ntiles; t += gridDim.x) {
        int r0 = t * 128;
        if (tid < 128) {
            int r = r0 + tid;
            inv[tid] = (r < N) ? 1.f / fmaxf(g_cnt[r], 1.f) : 0.f;
        }
        __syncthreads();
        #pragma unroll
        for (int c = 0; c < 16; c++) {
            int ci = c * 256 + tid;
            int m = ci >> 5, qq = ci & 31;
            int r = r0 + m;
            float4 v = {0.f, 0.f, 0.f, 0.f};
            if (r < N) v = ((const float4*)g_sums)[(size_t)r * 32 + qq];
            float iv = inv[m];
            uint2 pv = {pack_bf(v.x * iv, v.y * iv), pack_bf(v.z * iv, v.w * iv)};
            *(uint2*)((char*)As + (m * 136 + qq * 4) * 2) = pv;
        }
        __syncthreads();

        float acc[2][8][4];
        zero8(acc);
        wgemm<128, 136>(Ab, B2b, acc);

        uint32_t hlo[2][8], hhi[2][8];
        #pragma unroll
        for (int mt = 0; mt < 2; mt++)
            #pragma unroll
            for (int nt = 0; nt < 8; nt++) {
                int c0 = nw * 64 + nt * 8 + 2 * q;
                float2 bb = *(const float2*)(b2s + c0);
                hlo[mt][nt] = pack_bf(sp_fast(acc[mt][nt][0] + bb.x), sp_fast(acc[mt][nt][1] + bb.y));
                hhi[mt][nt] = pack_bf(sp_fast(acc[mt][nt][2] + bb.x), sp_fast(acc[mt][nt][3] + bb.y));
            }
        __syncthreads();
        #pragma unroll
        for (int mt = 0; mt < 2; mt++) {
            int r = mw * 32 + mt * 16 + g;
            #pragma unroll
            for (int nt = 0; nt < 8; nt++) {
                int c0 = nw * 64 + nt * 8 + 2 * q;
                *(uint32_t*)((char*)As + (r * 136 + c0) * 2) = hlo[mt][nt];
                *(uint32_t*)((char*)As + ((r + 8) * 136 + c0) * 2) = hhi[mt][nt];
            }
        }
        __syncthreads();

        zero8(acc);
        wgemm<128, 136>(Ab, B3b, acc);

        #pragma unroll
        for (int mt = 0; mt < 2; mt++) {
            int rlo = r0 + mw * 32 + mt * 16 + g, rhi = rlo + 8;
            #pragma unroll
            for (int nt = 0; nt < 8; nt++) {
                int c0 = nw * 64 + nt * 8 + 2 * q;
                float2 bb = *(const float2*)(b3s + c0);
                if (rlo < N) {
                    float2 nf = *(const float2*)(node_fea + (size_t)rlo * 128 + c0);
                    *(float2*)(out + (size_t)rlo * 128 + c0) =
                        make_float2(nf.x + acc[mt][nt][0] + bb.x, nf.y + acc[mt][nt][1] + bb.y);
                }
                if (rhi < N) {
                    float2 nf = *(const float2*)(node_fea + (size_t)rhi * 128 + c0);
                    *(float2*)(out + (size_t)rhi * 128 + c0) =
                        make_float2(nf.x + acc[mt][nt][2] + bb.x, nf.y + acc[mt][nt][3] + bb.y);
                }
            }
        }
        __syncthreads();
    }
}

extern "C" void kernel_launch(void* const* d_in, const int* in_sizes, int n_in,
                              void* d_out, int out_size) {
    const float* node_fea = (const float*)d_in[0];
    const int*   idx1     = (const int*)d_in[1];
    const int*   idx2     = (const int*)d_in[2];
    const float* edge_fea = (const float*)d_in[3];
    const float* W_aw1    = (const float*)d_in[4];
    const float* W_fg1    = (const float*)d_in[5];
    const float* b_fg1    = (const float*)d_in[6];
    const float* W_fg2    = (const float*)d_in[7];
    const float* b_fg2    = (const float*)d_in[8];
    const float* W_aw2    = (const float*)d_in[9];
    const float* b_aw2    = (const float*)d_in[10];
    const float* W_aw3    = (const float*)d_in[11];
    const float* b_aw3    = (const float*)d_in[12];

    int N = in_sizes[0] / 128;
    int E = in_sizes[1];
    float* out = (float*)d_out;

    void *p_sums, *p_cnt;
    cudaGetSymbolAddress(&p_sums, g_sums);
    cudaGetSymbolAddress(&p_cnt, g_cnt);
    cudaMemsetAsync(p_sums, 0, (size_t)N * 128 * sizeof(float));
    cudaMemsetAsync(p_cnt, 0, (size_t)N * sizeof(float));

    cudaFuncSetAttribute(gemm_x_mma, cudaFuncAttributeMaxDynamicSharedMemorySize, XK_SMEM);
    cudaFuncSetAttribute(edge_mma_kernel, cudaFuncAttributeMaxDynamicSharedMemorySize, EDGE_SMEM);
    cudaFuncSetAttribute(node_mma_kernel, cudaFuncAttributeMaxDynamicSharedMemorySize, NODE_SMEM);

    int ntN = (N + 127) / 128;
    int ntE = (E + 63) / 64;
    int gbN = ntN < 296 ? ntN : 296;
    int gbE = ntE < 296 ? ntE : 296;

    prep_weights<<<64, 256>>>(W_fg1, W_fg2, W_aw1, W_aw2, W_aw3);
    gemm_x_mma<<<gbN, 256, XK_SMEM>>>(node_fea, N, ntN);
    edge_mma_kernel<<<gbE, 256, EDGE_SMEM>>>(edge_fea, idx1, idx2, b_fg1, b_fg2, E, ntE);
    node_mma_kernel<<<gbN, 256, NODE_SMEM>>>(node_fea, b_aw2, b_aw3, out, N, ntN);
}

// round 15
// speedup vs baseline: 1.1272x; 1.0388x over previous
#include <cuda_runtime.h>
#include <cuda_bf16.h>
#include <math.h>
#include <stdint.h>

typedef unsigned long long u64;

#define NMAX 50000
#define EMAX 640000

__device__ float g_x[(size_t)NMAX * 128];
__device__ float g_sums[(size_t)NMAX * 128];
__device__ float g_cnt[NMAX];
__device__ __align__(16) char g_w1s[128 * 128];   // W_fg1^T, K=64, 128B/row, swizzled
__device__ __align__(16) char g_w2s[128 * 256];   // W_fg2^T, K=128, 256B/row, swizzled
__device__ __align__(16) __nv_bfloat16 g_wa1b[128 * 136];
__device__ __align__(16) __nv_bfloat16 g_wa2b[128 * 136];
__device__ __align__(16) __nv_bfloat16 g_wa3b[128 * 136];

__device__ __forceinline__ float sp_fast(float x) {
    float t = __expf(-fabsf(x));
    return fmaxf(x, 0.f) + __logf(1.f + t) - 0.69314718055994531f;
}
__device__ __forceinline__ uint32_t smem_u32(const void* p) {
    uint32_t a;
    asm("{ .reg .u64 t; cvta.to.shared.u64 t, %1; cvt.u32.u64 %0, t; }" : "=r"(a) : "l"(p));
    return a;
}
__device__ __forceinline__ void ldsm4(uint32_t& r0, uint32_t& r1, uint32_t& r2, uint32_t& r3, uint32_t addr) {
    asm volatile("ldmatrix.sync.aligned.m8n8.x4.shared.b16 {%0,%1,%2,%3}, [%4];"
                 : "=r"(r0), "=r"(r1), "=r"(r2), "=r"(r3) : "r"(addr));
}
__device__ __forceinline__ void mma16(float d[4], const uint32_t a[4], uint32_t b0, uint32_t b1) {
    asm("mma.sync.aligned.m16n8k16.row.col.f32.bf16.bf16.f32 "
        "{%0,%1,%2,%3}, {%4,%5,%6,%7}, {%8,%9}, {%0,%1,%2,%3};"
        : "+f"(d[0]), "+f"(d[1]), "+f"(d[2]), "+f"(d[3])
        : "r"(a[0]), "r"(a[1]), "r"(a[2]), "r"(a[3]), "r"(b0), "r"(b1));
}
__device__ __forceinline__ uint32_t pack_bf(float lo, float hi) {
    __nv_bfloat162 p = __floats2bfloat162_rn(lo, hi);
    return *(uint32_t*)&p;
}
__device__ __forceinline__ uint32_t swz2(int row, int chunk, int RB) {
    return (uint32_t)(row * RB + (((chunk ^ (row & 7)) & (RB / 16 - 1)) << 4));
}

// ---- swizzled warp GEMM, 32(m) x 32(n) warp tile (edge kernel) ----
template<int K, int RB>
__device__ __forceinline__ void wgemm_sw(uint32_t Au, int arow, int ak,
                                         uint32_t Bu, int brow0, int bk,
                                         float acc[2][4][4]) {
    #pragma unroll
    for (int kk = 0; kk < K; kk += 16) {
        int kc = kk >> 3;
        uint32_t a[2][4];
        #pragma unroll
        for (int mt = 0; mt < 2; mt++)
            ldsm4(a[mt][0], a[mt][1], a[mt][2], a[mt][3], Au + swz2(arow + mt * 16, kc + ak, RB));
        #pragma unroll
        for (int p = 0; p < 2; p++) {
            uint32_t b0, b1, b2, b3;
            ldsm4(b0, b1, b2, b3, Bu + swz2(brow0 + p * 16, kc + bk, RB));
            mma16(acc[0][2 * p], a[0], b0, b1);
            mma16(acc[1][2 * p], a[1], b0, b1);
            mma16(acc[0][2 * p + 1], a[0], b2, b3);
            mma16(acc[1][2 * p + 1], a[1], b2, b3);
        }
    }
}

__device__ __forceinline__ void zero8(float acc[2][8][4]) {
    #pragma unroll
    for (int a = 0; a < 2; a++)
        #pragma unroll
        for (int b = 0; b < 8; b++)
            #pragma unroll
            for (int c = 0; c < 4; c++) acc[a][b][c] = 0.f;
}
// ---- padded non-swizzled warp GEMM (node / x kernels), 32x64 tile ----
template<int K, int S>
__device__ __forceinline__ void wgemm(uint32_t Abase, uint32_t Bbase, float acc[2][8][4]) {
    #pragma unroll
    for (int kk = 0; kk < K; kk += 16) {
        uint32_t a[2][4];
        #pragma unroll
        for (int mt = 0; mt < 2; mt++)
            ldsm4(a[mt][0], a[mt][1], a[mt][2], a[mt][3], Abase + (mt * 16 * S + kk) * 2);
        #pragma unroll
        for (int p = 0; p < 4; p++) {
            uint32_t b0, b1, b2, b3;
            ldsm4(b0, b1, b2, b3, Bbase + (p * 16 * S + kk) * 2);
            mma16(acc[0][2 * p], a[0], b0, b1);
            mma16(acc[1][2 * p], a[1], b0, b1);
            mma16(acc[0][2 * p + 1], a[0], b2, b3);
            mma16(acc[1][2 * p + 1], a[1], b2, b3);
        }
    }
}

__global__ void prep_weights(const float* __restrict__ W1, const float* __restrict__ W2,
                             const float* __restrict__ Wa1, const float* __restrict__ Wa2,
                             const float* __restrict__ Wa3) {
    int t = blockIdx.x * blockDim.x + threadIdx.x;
    int stride = blockDim.x * gridDim.x;
    for (int i = t; i < 64 * 128; i += stride) {
        int k = i >> 7, n = i & 127;
        *(__nv_bfloat16*)(g_w1s + swz2(n, k >> 3, 128) + (k & 7) * 2) = __float2bfloat16(W1[i]);
    }
    for (int i = t; i < 128 * 128; i += stride) {
        int k = i >> 7, n = i & 127;
        *(__nv_bfloat16*)(g_w2s + swz2(n, k >> 3, 256) + (k & 7) * 2) = __float2bfloat16(W2[i]);
        g_wa1b[n * 136 + k] = __float2bfloat16(Wa1[i]);
        g_wa2b[n * 136 + k] = __float2bfloat16(Wa2[i]);
        g_wa3b[n * 136 + k] = __float2bfloat16(Wa3[i]);
    }
}

// ---------------- Kernel 1: x = node_fea @ W_aw1 + zero sums/cnt ----------------
#define XK_SMEM ((128 * 136 * 2) * 2)
__global__ __launch_bounds__(256, 2) void gemm_x_mma(const float* __restrict__ A,
                                                     int N, int ntiles) {
    extern __shared__ char smc[];
    __nv_bfloat16* Wt = (__nv_bfloat16*)smc;
    __nv_bfloat16* As = Wt + 128 * 136;
    int tid = threadIdx.x, wid = tid >> 5, lane = tid & 31;
    int g = lane >> 2, q = lane & 3;
    int mw = wid & 3, nw = wid >> 2;
    int arow = (lane & 7) + ((lane >> 3) & 1) * 8, ak = lane >> 4;
    int brow = (lane & 7) + ((lane >> 4) << 3), bk = (lane >> 3) & 1;

    for (int i = tid; i < 128 * 136 * 2 / 16; i += 256) ((uint4*)Wt)[i] = ((const uint4*)g_wa1b)[i];
    uint32_t Ab = smem_u32(As) + ((mw * 32 + arow) * 136 + ak * 8) * 2;
    uint32_t Bb = smem_u32(Wt) + ((nw * 64 + brow) * 136 + bk * 8) * 2;

    const float4 zf4 = {0.f, 0.f, 0.f, 0.f};
    for (int t = blockIdx.x; t < ntiles; t += gridDim.x) {
        int r0 = t * 128;
        #pragma unroll
        for (int c = 0; c < 16; c++) {
            int ci = c * 256 + tid;
            int m = ci >> 5, qq = ci & 31;
            int r = r0 + m;
            float4 v = zf4;
            if (r < N) {
                v = ((const float4*)A)[(size_t)r * 32 + qq];
                ((float4*)g_sums)[(size_t)r * 32 + qq] = zf4;   // zero sums (fused memset)
            }
            uint2 pv = {pack_bf(v.x, v.y), pack_bf(v.z, v.w)};
            *(uint2*)((char*)As + (m * 136 + qq * 4) * 2) = pv;
        }
        if (tid < 128) {
            int r = r0 + tid;
            if (r < N) g_cnt[r] = 0.f;                          // zero cnt (fused memset)
        }
        __syncthreads();
        float acc[2][8][4];
        zero8(acc);
        wgemm<128, 136>(Ab, Bb, acc);
        #pragma unroll
        for (int mt = 0; mt < 2; mt++) {
            int rlo = r0 + mw * 32 + mt * 16 + g, rhi = rlo + 8;
            #pragma unroll
            for (int nt = 0; nt < 8; nt++) {
                int c0 = nw * 64 + nt * 8 + 2 * q;
                if (rlo < N) *(float2*)(g_x + (size_t)rlo * 128 + c0) = make_float2(acc[mt][nt][0], acc[mt][nt][1]);
                if (rhi < N) *(float2*)(g_x + (size_t)rhi * 128 + c0) = make_float2(acc[mt][nt][2], acc[mt][nt][3]);
            }
        }
        __syncthreads();
    }
}

// ---------------- Kernel 2: persistent bf16-MMA edge pipeline (R11 + bf16-w P) ----------------
// smem: W1 16K @0, W2 32K @16384, A1 8K @49152, A2 16K @57344, P(bf16 w) 16K @73728
//       b1s @90112, b2s @90624, i1s @91136, i2s @91392   total 91648
#define EW1 0
#define EW2 16384
#define EA1 49152
#define EA2 57344
#define EP  73728
#define EB1 90112
#define EB2 90624
#define EI1 91136
#define EI2 91392
#define EDGE_SMEM 91648

__global__ __launch_bounds__(256, 2) void edge_mma_kernel(const float* __restrict__ ef,
                                                          const int* __restrict__ idx1,
                                                          const int* __restrict__ idx2,
                                                          const float* __restrict__ b1,
                                                          const float* __restrict__ b2,
                                                          int E, int ntiles) {
    extern __shared__ char smc[];
    float* b1s = (float*)(smc + EB1);
    float* b2s = (float*)(smc + EB2);
    int* i1s = (int*)(smc + EI1);
    int* i2s = (int*)(smc + EI2);

    int tid = threadIdx.x, wid = tid >> 5, lane = tid & 31;
    int g = lane >> 2, q = lane & 3;
    int mw = wid >> 2, nw = wid & 3;          // 2(m) x 4(n) warp grid, 32x32 tiles
    int arow_l = (lane & 7) + ((lane >> 3) & 1) * 8, ak = lane >> 4;
    int brow_l = (lane & 7) + ((lane >> 4) << 3), bk = (lane >> 3) & 1;
    const float4* ef4 = (const float4*)ef;

    uint32_t sb = smem_u32(smc);
    uint32_t W1u = sb + EW1, W2u = sb + EW2, A1u = sb + EA1, A2u = sb + EA2;

    for (int i = tid; i < 16384 / 16; i += 256) ((uint4*)(smc + EW1))[i] = ((const uint4*)g_w1s)[i];
    for (int i = tid; i < 32768 / 16; i += 256) ((uint4*)(smc + EW2))[i] = ((const uint4*)g_w2s)[i];
    if (tid < 128) { b1s[tid] = b1[tid]; b2s[tid] = b2[tid]; }

    int arow = mw * 32 + arow_l;
    int brow0 = nw * 32 + brow_l;

    int t = blockIdx.x;
    if (t < ntiles) {
        int e0 = t * 64;
        #pragma unroll
        for (int c = 0; c < 4; c++) {
            int ci = c * 256 + tid;
            int m = ci >> 4, qq = ci & 15;
            int e = e0 + m;
            float4 v = {0.f, 0.f, 0.f, 0.f};
            if (e < E) v = ef4[(size_t)e * 16 + qq];
            uint2 pv = {pack_bf(v.x, v.y), pack_bf(v.z, v.w)};
            *(uint2*)(smc + EA1 + swz2(m, qq >> 1, 128) + (qq & 1) * 8) = pv;
        }
        if (tid < 128) {
            int e = e0 + (tid & 63);
            int v = (e < E) ? ((tid < 64) ? idx1[e] : idx2[e]) : 0;
            if (tid < 64) i1s[tid] = v; else i2s[tid - 64] = v;
        }
    }
    __syncthreads();

    for (; t < ntiles; t += gridDim.x) {
        int e0 = t * 64;
        int tn = t + gridDim.x;
        bool have_next = tn < ntiles;

        // register-prefetch next tile's edge features + indices
        float4 pf[4];
        int pidx = 0;
        if (have_next) {
            int ee0 = tn * 64;
            #pragma unroll
            for (int c = 0; c < 4; c++) {
                int ci = c * 256 + tid;
                int m = ci >> 4, qq = ci & 15;
                int e = ee0 + m;
                float4 v = {0.f, 0.f, 0.f, 0.f};
                if (e < E) v = ef4[(size_t)e * 16 + qq];
                pf[c] = v;
            }
            if (tid < 128) {
                int e = ee0 + (tid & 63);
                if (e < E) pidx = (tid < 64) ? idx1[e] : idx2[e];
            }
        }

        // current tile indices + row-coalesced x-gathers (land during GEMMs)
        float4 xg[8];
        int n1r[8];
        #pragma unroll
        for (int j = 0; j < 8; j++) {
            int r = wid * 8 + j;
            int n2 = i2s[r];
            n1r[j] = i1s[r];
            xg[j] = *(const float4*)(g_x + (size_t)n2 * 128 + lane * 4);
        }

        // ---- GEMM1: h = A1 @ W1^T (K=64) ----
        float acc[2][4][4];
        #pragma unroll
        for (int a = 0; a < 2; a++)
            #pragma unroll
            for (int b = 0; b < 4; b++)
                #pragma unroll
                for (int c = 0; c < 4; c++) acc[a][b][c] = 0.f;
        wgemm_sw<64, 128>(A1u, arow, ak, W1u, brow0, bk, acc);

        // ---- epilogue 1: A2 = bf16(sp(h + b1)) ----
        #pragma unroll
        for (int mt = 0; mt < 2; mt++) {
            int r = mw * 32 + mt * 16 + g;
            #pragma unroll
            for (int nt = 0; nt < 4; nt++) {
                int c0 = nw * 32 + nt * 8 + 2 * q;
                float2 bb = *(const float2*)(b1s + c0);
                uint32_t lo = pack_bf(sp_fast(acc[mt][nt][0] + bb.x), sp_fast(acc[mt][nt][1] + bb.y));
                uint32_t hi = pack_bf(sp_fast(acc[mt][nt][2] + bb.x), sp_fast(acc[mt][nt][3] + bb.y));
                int chunk = c0 >> 3, inner = (c0 & 7) * 2;
                *(uint32_t*)(smc + EA2 + swz2(r, chunk, 256) + inner) = lo;
                *(uint32_t*)(smc + EA2 + swz2(r + 8, chunk, 256) + inner) = hi;
            }
        }
        __syncthreads();   // syncA

        // store next tile's A1 + indices (overlaps GEMM2)
        if (have_next) {
            #pragma unroll
            for (int c = 0; c < 4; c++) {
                int ci = c * 256 + tid;
                int m = ci >> 4, qq = ci & 15;
                uint2 pv = {pack_bf(pf[c].x, pf[c].y), pack_bf(pf[c].z, pf[c].w)};
                *(uint2*)(smc + EA1 + swz2(m, qq >> 1, 128) + (qq & 1) * 8) = pv;
            }
            if (tid < 128) {
                if (tid < 64) i1s[tid] = pidx; else i2s[tid - 64] = pidx;
            }
        }

        // ---- GEMM2: W = A2 @ W2^T (K=128) ----
        #pragma unroll
        for (int a = 0; a < 2; a++)
            #pragma unroll
            for (int b = 0; b < 4; b++)
                #pragma unroll
                for (int c = 0; c < 4; c++) acc[a][b][c] = 0.f;
        wgemm_sw<128, 256>(A2u, arow, ak, W2u, brow0, bk, acc);

        // ---- dump w = bf16(sp(acc + b2)) into P (bias pre-applied) ----
        #pragma unroll
        for (int mt = 0; mt < 2; mt++) {
            int rlo = mw * 32 + mt * 16 + g, rhi = rlo + 8;
            #pragma unroll
            for (int nt = 0; nt < 4; nt++) {
                int c0 = nw * 32 + nt * 8 + 2 * q;
                float2 bb = *(const float2*)(b2s + c0);
                uint32_t lo = pack_bf(sp_fast(acc[mt][nt][0] + bb.x), sp_fast(acc[mt][nt][1] + bb.y));
                uint32_t hi = pack_bf(sp_fast(acc[mt][nt][2] + bb.x), sp_fast(acc[mt][nt][3] + bb.y));
                int chunk = c0 >> 3, inner = (c0 & 7) * 2;
                *(uint32_t*)(smc + EP + swz2(rlo, chunk, 256) + inner) = lo;
                *(uint32_t*)(smc + EP + swz2(rhi, chunk, 256) + inner) = hi;
            }
        }
        __syncthreads();   // syncB

        // ---- row pass: warp owns 8 edges; LDS.64 w + gather-mul + red.v4 ----
        {
            #pragma unroll
            for (int j = 0; j < 8; j++) {
                int r = wid * 8 + j;
                int e = e0 + r;
                uint2 wv = *(const uint2*)(smc + EP + (r << 8) +
                                           ((((lane >> 1) ^ (r & 7)) & 15) << 4) + (lane & 1) * 8);
                float2 wlo = __bfloat1622float2(*(__nv_bfloat162*)&wv.x);
                float2 whi = __bfloat1622float2(*(__nv_bfloat162*)&wv.y);
                float4 xv = xg[j];
                float a0 = wlo.x * xv.x;
                float a1 = wlo.y * xv.y;
                float a2 = whi.x * xv.z;
                float a3 = whi.y * xv.w;
                if (e < E) {
                    asm volatile("red.global.add.v4.f32 [%0], {%1,%2,%3,%4};"
                                 :: "l"(g_sums + (size_t)n1r[j] * 128 + lane * 4),
                                    "f"(a0), "f"(a1), "f"(a2), "f"(a3) : "memory");
                    if (lane == 0) atomicAdd(&g_cnt[n1r[j]], 1.0f);
                }
            }
        }
        // no sync: next iteration's syncA separates P reads from next P writes
    }
}

// ---------------- Kernel 3: node epilogue (bf16 MMA, persistent — R11 version) ----------------
#define NODE_SMEM ((128 * 136 * 3) * 2 + 128 * 4 * 3)
__global__ __launch_bounds__(256, 2) void node_mma_kernel(const float* __restrict__ node_fea,
                                                          const float* __restrict__ baw2,
                                                          const float* __restrict__ baw3,
                                                          float* __restrict__ out,
                                                          int N, int ntiles) {
    extern __shared__ char smc[];
    __nv_bfloat16* W2t = (__nv_bfloat16*)smc;
    __nv_bfloat16* W3t = W2t + 128 * 136;
    __nv_bfloat16* As  = W3t + 128 * 136;
    float* inv = (float*)(As + 128 * 136);
    float* b2s = inv + 128;
    float* b3s = b2s + 128;

    int tid = threadIdx.x, wid = tid >> 5, lane = tid & 31;
    int g = lane >> 2, q = lane & 3;
    int mw = wid & 3, nw = wid >> 2;
    int arow = (lane & 7) + ((lane >> 3) & 1) * 8, ak = lane >> 4;
    int brow = (lane & 7) + ((lane >> 4) << 3), bk = (lane >> 3) & 1;

    for (int i = tid; i < 128 * 136 * 2 / 16; i += 256) {
        ((uint4*)W2t)[i] = ((const uint4*)g_wa2b)[i];
        ((uint4*)W3t)[i] = ((const uint4*)g_wa3b)[i];
    }
    if (tid < 128) { b2s[tid] = baw2[tid]; b3s[tid] = baw3[tid]; }

    uint32_t Ab = smem_u32(As) + ((mw * 32 + arow) * 136 + ak * 8) * 2;
    uint32_t B2b = smem_u32(W2t) + ((nw * 64 + brow) * 136 + bk * 8) * 2;
    uint32_t B3b = smem_u32(W3t) + ((nw * 64 + brow) * 136 + bk * 8) * 2;

    for (int t = blockIdx.x; t < ntiles; t += gridDim.x) {
        int r0 = t * 128;
        if (tid < 128) {
            int r = r0 + tid;
            inv[tid] = (r < N) ? 1.f / fmaxf(g_cnt[r], 1.f) : 0.f;
        }
        __syncthreads();
        #pragma unroll
        for (int c = 0; c < 16; c++) {
            int ci = c * 256 + tid;
            int m = ci >> 5, qq = ci & 31;
            int r = r0 + m;
            float4 v = {0.f, 0.f, 0.f, 0.f};
            if (r < N) v = ((const float4*)g_sums)[(size_t)r * 32 + qq];
            float iv = inv[m];
            uint2 pv = {pack_bf(v.x * iv, v.y * iv), pack_bf(v.z * iv, v.w * iv)};
            *(uint2*)((char*)As + (m * 136 + qq * 4) * 2) = pv;
        }
        __syncthreads();

        float acc[2][8][4];
        zero8(acc);
        wgemm<128, 136>(Ab, B2b, acc);

        uint32_t hlo[2][8], hhi[2][8];
        #pragma unroll
        for (int mt = 0; mt < 2; mt++)
            #pragma unroll
            for (int nt = 0; nt < 8; nt++) {
                int c0 = nw * 64 + nt * 8 + 2 * q;
                float2 bb = *(const float2*)(b2s + c0);
                hlo[mt][nt] = pack_bf(sp_fast(acc[mt][nt][0] + bb.x), sp_fast(acc[mt][nt][1] + bb.y));
                hhi[mt][nt] = pack_bf(sp_fast(acc[mt][nt][2] + bb.x), sp_fast(acc[mt][nt][3] + bb.y));
            }
        __syncthreads();
        #pragma unroll
        for (int mt = 0; mt < 2; mt++) {
            int r = mw * 32 + mt * 16 + g;
            #pragma unroll
            for (int nt = 0; nt < 8; nt++) {
                int c0 = nw * 64 + nt * 8 + 2 * q;
                *(uint32_t*)((char*)As + (r * 136 + c0) * 2) = hlo[mt][nt];
                *(uint32_t*)((char*)As + ((r + 8) * 136 + c0) * 2) = hhi[mt][nt];
            }
        }
        __syncthreads();

        zero8(acc);
        wgemm<128, 136>(Ab, B3b, acc);

        #pragma unroll
        for (int mt = 0; mt < 2; mt++) {
            int rlo = r0 + mw * 32 + mt * 16 + g, rhi = rlo + 8;
            #pragma unroll
            for (int nt = 0; nt < 8; nt++) {
                int c0 = nw * 64 + nt * 8 + 2 * q;
                float2 bb = *(const float2*)(b3s + c0);
                if (rlo < N) {
                    float2 nf = *(const float2*)(node_fea + (size_t)rlo * 128 + c0);
                    *(float2*)(out + (size_t)rlo * 128 + c0) =
                        make_float2(nf.x + acc[mt][nt][0] + bb.x, nf.y + acc[mt][nt][1] + bb.y);
                }
                if (rhi < N) {
                    float2 nf = *(const float2*)(node_fea + (size_t)rhi * 128 + c0);
                    *(float2*)(out + (size_t)rhi * 128 + c0) =
                        make_float2(nf.x + acc[mt][nt][2] + bb.x, nf.y + acc[mt][nt][3] + bb.y);
                }
            }
        }
        __syncthreads();
    }
}

extern "C" void kernel_launch(void* const* d_in, const int* in_sizes, int n_in,
                              void* d_out, int out_size) {
    const float* node_fea = (const float*)d_in[0];
    const int*   idx1     = (const int*)d_in[1];
    const int*   idx2     = (const int*)d_in[2];
    const float* edge_fea = (const float*)d_in[3];
    const float* W_aw1    = (const float*)d_in[4];
    const float* W_fg1    = (const float*)d_in[5];
    const float* b_fg1    = (const float*)d_in[6];
    const float* W_fg2    = (const float*)d_in[7];
    const float* b_fg2    = (const float*)d_in[8];
    const float* W_aw2    = (const float*)d_in[9];
    const float* b_aw2    = (const float*)d_in[10];
    const float* W_aw3    = (const float*)d_in[11];
    const float* b_aw3    = (const float*)d_in[12];

    int N = in_sizes[0] / 128;
    int E = in_sizes[1];
    float* out = (float*)d_out;

    cudaFuncSetAttribute(gemm_x_mma, cudaFuncAttributeMaxDynamicSharedMemorySize, XK_SMEM);
    cudaFuncSetAttribute(edge_mma_kernel, cudaFuncAttributeMaxDynamicSharedMemorySize, EDGE_SMEM);
    cudaFuncSetAttribute(node_mma_kernel, cudaFuncAttributeMaxDynamicSharedMemorySize, NODE_SMEM);

    int ntN = (N + 127) / 128;
    int ntE = (E + 63) / 64;
    int gbN = ntN < 296 ? ntN : 296;
    int gbE = ntE < 296 ? ntE : 296;

    prep_weights<<<64, 256>>>(W_fg1, W_fg2, W_aw1, W_aw2, W_aw3);
    gemm_x_mma<<<gbN, 256, XK_SMEM>>>(node_fea, N, ntN);   // also zeroes g_sums / g_cnt
    edge_mma_kernel<<<gbE, 256, EDGE_SMEM>>>(edge_fea, idx1, idx2, b_fg1, b_fg2, E, ntE);
    node_mma_kernel<<<gbN, 256, NODE_SMEM>>>(node_fea, b_aw2, b_aw3, out, N, ntN);
}